// round 1
// baseline (speedup 1.0000x reference)
#include <cuda_runtime.h>
#include <cuda_bf16.h>
#include <math.h>

#define Bb 8
#define Nn 8192
#define Ss 2048
#define Kk 32
#define EPSc 1e-5f
#define ALPHAc 0.2f

// ---------------- scratch (device globals; no allocations) ----------------
__device__ int   g_fps_idx[Bb * Ss];
__device__ int   g_ball_idx[Bb * Ss * Kk];
__device__ float g_newxyz[Bb * Ss * 3];
__device__ float g_F[(size_t)Bb * Nn * 64];        // 16.8 MB: [xyz(3) | points(61)] per point
__device__ float g_W0[64 * 64], g_b0[64];
__device__ float g_W1[64 * 64], g_b1[64];
__device__ float g_W2[128 * 64], g_b2[128];

// ---------------- FPS: one block per batch ----------------
__global__ void __launch_bounds__(1024) fps_kernel(const float* __restrict__ xyz) {
    extern __shared__ float smem[];
    float* xs = smem;
    float* ys = smem + Nn;
    float* zs = smem + 2 * Nn;
    __shared__ float rv[32];
    __shared__ int   ri[32];
    __shared__ int   sm_cur;

    int b = blockIdx.x;
    int tid = threadIdx.x;
    int lane = tid & 31, wid = tid >> 5;

    float px[8], py[8], pz[8], dd[8];
#pragma unroll
    for (int j = 0; j < 8; j++) {
        int i = tid + j * 1024;
        px[j] = xyz[((size_t)b * 3 + 0) * Nn + i];
        py[j] = xyz[((size_t)b * 3 + 1) * Nn + i];
        pz[j] = xyz[((size_t)b * 3 + 2) * Nn + i];
        xs[i] = px[j]; ys[i] = py[j]; zs[i] = pz[j];
        dd[j] = 1e10f;
    }
    if (tid == 0) sm_cur = 0;
    __syncthreads();

    for (int s = 0; s < Ss; s++) {
        int cur = sm_cur;
        if (tid == 0) g_fps_idx[b * Ss + s] = cur;
        float cx = xs[cur], cy = ys[cur], cz = zs[cur];

        float best = -1.0f; int bi = 0;
#pragma unroll
        for (int j = 0; j < 8; j++) {
            float dx = px[j] - cx, dy = py[j] - cy, dz = pz[j] - cz;
            float d = dx * dx + dy * dy + dz * dz;
            float nd = fminf(dd[j], d);
            dd[j] = nd;
            if (nd > best) { best = nd; bi = tid + j * 1024; }  // ascending idx -> first max
        }
#pragma unroll
        for (int off = 16; off; off >>= 1) {
            float ov = __shfl_down_sync(0xffffffffu, best, off);
            int   oi = __shfl_down_sync(0xffffffffu, bi, off);
            if (ov > best || (ov == best && oi < bi)) { best = ov; bi = oi; }
        }
        if (lane == 0) { rv[wid] = best; ri[wid] = bi; }
        __syncthreads();
        if (wid == 0) {
            best = rv[lane]; bi = ri[lane];
#pragma unroll
            for (int off = 16; off; off >>= 1) {
                float ov = __shfl_down_sync(0xffffffffu, best, off);
                int   oi = __shfl_down_sync(0xffffffffu, bi, off);
                if (ov > best || (ov == best && oi < bi)) { best = ov; bi = oi; }
            }
            if (lane == 0) sm_cur = bi;
        }
        __syncthreads();
    }
}

// ---------------- gather centers: new_xyz, new_targets ----------------
__global__ void __launch_bounds__(256) gather_kernel(const float* __restrict__ xyz,
                                                     const int* __restrict__ tgt,
                                                     float* __restrict__ out) {
    int t = blockIdx.x * 256 + threadIdx.x;   // exactly B*S threads
    int b = t >> 11, s = t & 2047;
    int i = g_fps_idx[t];
    float x = xyz[((size_t)b * 3 + 0) * Nn + i];
    float y = xyz[((size_t)b * 3 + 1) * Nn + i];
    float z = xyz[((size_t)b * 3 + 2) * Nn + i];
    g_newxyz[t * 3 + 0] = x;
    g_newxyz[t * 3 + 1] = y;
    g_newxyz[t * 3 + 2] = z;
    out[((size_t)b * 3 + 0) * Ss + s] = x;
    out[((size_t)b * 3 + 1) * Ss + s] = y;
    out[((size_t)b * 3 + 2) * Ss + s] = z;
    out[(size_t)Bb * 3 * Ss + (size_t)Bb * 128 * Ss + t] = (float)tgt[(size_t)b * Nn + i];
}

// ---------------- build F[b][n][64] = [xyz(3) | points(61)] (smem transpose) ----
__global__ void __launch_bounds__(256) buildF_kernel(const float* __restrict__ xyz,
                                                     const float* __restrict__ pts) {
    __shared__ float tile[64][65];
    int b = blockIdx.x / (Nn / 64);
    int n0 = (blockIdx.x % (Nn / 64)) * 64;
    int nl = threadIdx.x & 63;
    int cl = threadIdx.x >> 6;       // 0..3
    for (int c = cl; c < 64; c += 4) {
        int n = n0 + nl;
        float v = (c < 3) ? xyz[((size_t)b * 3 + c) * Nn + n]
                          : pts[((size_t)b * 61 + (c - 3)) * Nn + n];
        tile[c][nl] = v;
    }
    __syncthreads();
    int c = threadIdx.x & 63;
    int nb = threadIdx.x >> 6;
    for (int nn = nb; nn < 64; nn += 4)
        g_F[((size_t)(b * Nn + n0 + nn)) * 64 + c] = tile[c][nn];
}

// ---------------- fold BN into weights ----------------
__global__ void __launch_bounds__(256) fold_kernel(
    const float* w0, const float* b0, const float* g0, const float* be0, const float* m0, const float* v0,
    const float* w1, const float* b1, const float* g1, const float* be1, const float* m1, const float* v1,
    const float* w2, const float* b2, const float* g2, const float* be2, const float* m2, const float* v2) {
    int t = blockIdx.x * 256 + threadIdx.x;
    if (t < 4096) {
        int o = t >> 6;
        float sc = g0[o] / sqrtf(v0[o] + EPSc);
        g_W0[t] = w0[t] * sc;
        if ((t & 63) == 0) g_b0[o] = (b0[o] - m0[o]) * sc + be0[o];
    } else if (t < 8192) {
        int i = t - 4096; int o = i >> 6;
        float sc = g1[o] / sqrtf(v1[o] + EPSc);
        g_W1[i] = w1[i] * sc;
        if ((i & 63) == 0) g_b1[o] = (b1[o] - m1[o]) * sc + be1[o];
    } else if (t < 16384) {
        int i = t - 8192; int o = i >> 6;
        float sc = g2[o] / sqrtf(v2[o] + EPSc);
        g_W2[i] = w2[i] * sc;
        if ((i & 63) == 0) g_b2[o] = (b2[o] - m2[o]) * sc + be2[o];
    }
}

// ---------------- ball query: one warp per group, scan indices ascending ------
__global__ void __launch_bounds__(256) ball_kernel(const float* __restrict__ xyz) {
    int gw = blockIdx.x * 8 + (threadIdx.x >> 5);   // group id 0..16383
    int lane = threadIdx.x & 31;
    int b = gw >> 11;
    float cx = g_newxyz[gw * 3 + 0];
    float cy = g_newxyz[gw * 3 + 1];
    float cz = g_newxyz[gw * 3 + 2];
    const float* xb = xyz + (size_t)b * 3 * Nn;
    int cnt = 0, firstn = 0;
    for (int base = 0; base < Nn; base += 32) {
        int n = base + lane;
        float dx = xb[n] - cx, dy = xb[Nn + n] - cy, dz = xb[2 * Nn + n] - cz;
        float d = dx * dx + dy * dy + dz * dz;
        bool inb = (d <= 0.25f);
        unsigned m = __ballot_sync(0xffffffffu, inb);
        if (cnt == 0 && m) firstn = base + __ffs(m) - 1;
        int pos = cnt + __popc(m & ((1u << lane) - 1u));
        if (inb && pos < Kk) g_ball_idx[(size_t)gw * Kk + pos] = n;
        cnt += __popc(m);
        if (cnt >= Kk) break;
    }
    for (int j = cnt + lane; j < Kk; j += 32)
        g_ball_idx[(size_t)gw * Kk + j] = firstn;
}

// ---------------- fused MLP + attention, one block per group ----------------
// smem layout (floats): bufA[33*68] bufB[33*68] gf[33*132] Wsh[128*68] bsh[128] dp[96]
template <int COUT>
__device__ __forceinline__ void mlp_layer(const float* __restrict__ Wg,
                                          const float* __restrict__ bg,
                                          float* Wsh, float* bsh,
                                          const float* in, float* out,
                                          int outStride, int tid) {
    __syncthreads();
    for (int idx = tid; idx < COUT * 64; idx += 256) {
        int o = idx >> 6, c = idx & 63;
        Wsh[o * 68 + c] = Wg[idx];
    }
    if (tid < COUT) bsh[tid] = bg[tid];
    __syncthreads();

    int w = tid >> 5, lane = tid & 31;
#pragma unroll
    for (int pass = 0; pass < COUT / 64; pass++) {
        int o0 = pass * 64 + w * 8;
        float acc[8];
#pragma unroll
        for (int j = 0; j < 8; j++) acc[j] = 0.0f;
        const float4* inr = (const float4*)(in + lane * 68);
#pragma unroll
        for (int cc = 0; cc < 16; cc++) {
            float4 iv = inr[cc];
#pragma unroll
            for (int j = 0; j < 8; j++) {
                float4 wv = *(const float4*)(Wsh + (o0 + j) * 68 + cc * 4);
                acc[j] += iv.x * wv.x + iv.y * wv.y + iv.z * wv.z + iv.w * wv.w;
            }
        }
#pragma unroll
        for (int j = 0; j < 8; j++)
            out[lane * outStride + o0 + j] = fmaxf(acc[j] + bsh[o0 + j], 0.0f);
    }
    // center row (p = 32)
    if (tid < COUT) {
        float acc = 0.0f;
#pragma unroll 8
        for (int c = 0; c < 64; c++) acc += Wsh[tid * 68 + c] * in[32 * 68 + c];
        out[32 * outStride + tid] = fmaxf(acc + bsh[tid], 0.0f);
    }
}

__global__ void __launch_bounds__(256) fused_kernel(const float* __restrict__ a_g,
                                                    float* __restrict__ d_out) {
    extern __shared__ float sm[];
    float* bufA = sm;                 // 2244
    float* bufB = sm + 2244;          // 2244
    float* gf   = sm + 4488;          // 4356
    float* Wsh  = sm + 8844;          // 8704
    float* bsh  = sm + 17548;         // 128
    float* dpx  = sm + 17676;         // 32
    float* dpy  = dpx + 32;
    float* dpz  = dpy + 32;

    int tid = threadIdx.x;
    int g = blockIdx.x;
    int b = g >> 11, s = g & 2047;
    int w = tid >> 5, lane = tid & 31;

    // ---- load 33 feature rows (0..31 neighbors, 32 center) ----
    for (int p = w; p < 33; p += 8) {
        int src = (p < 32) ? g_ball_idx[(size_t)g * Kk + p] : g_fps_idx[g];
        const float2* rowp = (const float2*)(g_F + (size_t)(b * Nn + src) * 64);
        float2 v = rowp[lane];
        bufA[p * 68 + lane * 2]     = v.x;
        bufA[p * 68 + lane * 2 + 1] = v.y;
    }
    __syncthreads();
    if (tid < 32) {
        int k = tid;
        float nx = g_newxyz[g * 3 + 0];
        float ny = g_newxyz[g * 3 + 1];
        float nz = g_newxyz[g * 3 + 2];
        float gx = bufA[k * 68 + 0], gy = bufA[k * 68 + 1], gz = bufA[k * 68 + 2];
        bufA[k * 68 + 0] = gx - nx;   // grouped_norm
        bufA[k * 68 + 1] = gy - ny;
        bufA[k * 68 + 2] = gz - nz;
        dpx[k] = nx - gx;             // delta_p
        dpy[k] = ny - gy;
        dpz[k] = nz - gz;
    }

    // ---- 3-layer MLP ----
    mlp_layer<64>(g_W0, g_b0, Wsh, bsh, bufA, bufB, 68, tid);
    mlp_layer<64>(g_W1, g_b1, Wsh, bsh, bufB, bufA, 68, tid);
    mlp_layer<128>(g_W2, g_b2, Wsh, bsh, bufA, gf, 132, tid);
    __syncthreads();

    // ---- build cat[32][132] = [delta_p(3) | cf - gf (128) | 0] ----
    float* cat = bufA;  // bufA+bufB contiguous: 4488 floats >= 32*132
    for (int idx = tid; idx < 32 * 131; idx += 256) {
        int k = idx / 131;
        int c = idx - k * 131;
        float v;
        if (c == 0) v = dpx[k];
        else if (c == 1) v = dpy[k];
        else if (c == 2) v = dpz[k];
        else v = gf[32 * 132 + (c - 3)] - gf[k * 132 + (c - 3)];
        cat[k * 132 + c] = v;
    }
    if (tid < 32) cat[tid * 132 + 131] = 0.0f;

    // ---- e = cat @ a  (131 -> 128), tiled over c; acc in regs ----
    float acc[16];
#pragma unroll
    for (int j = 0; j < 16; j++) acc[j] = 0.0f;
    for (int t = 0; t < 3; t++) {
        int c0 = t * 64;
        int tw = (t < 2) ? 64 : 4;
        __syncthreads();
        for (int idx = tid; idx < 128 * tw; idx += 256) {
            int d = idx & 127, cc = idx >> 7;
            int c = c0 + cc;
            Wsh[d * 68 + cc] = (c < 131) ? a_g[(size_t)c * 128 + d] : 0.0f;
        }
        __syncthreads();
        const float4* inr = (const float4*)(cat + lane * 132 + c0);
        int nch = tw >> 2;
        for (int cc = 0; cc < nch; cc++) {
            float4 iv = inr[cc];
#pragma unroll
            for (int pass = 0; pass < 2; pass++)
#pragma unroll
                for (int j = 0; j < 8; j++) {
                    int o = pass * 64 + w * 8 + j;
                    float4 wv = *(const float4*)(Wsh + o * 68 + cc * 4);
                    acc[pass * 8 + j] += iv.x * wv.x + iv.y * wv.y + iv.z * wv.z + iv.w * wv.w;
                }
        }
    }

    // ---- leaky relu + softmax over k (lanes) + weighted sum ----
    const unsigned FULL = 0xffffffffu;
    float* outp = d_out + (size_t)Bb * 3 * Ss + (size_t)b * 128 * Ss + s;
#pragma unroll
    for (int pass = 0; pass < 2; pass++)
#pragma unroll
        for (int j = 0; j < 8; j++) {
            int d = pass * 64 + w * 8 + j;
            float e = acc[pass * 8 + j];
            e = (e >= 0.0f) ? e : (ALPHAc * e);
            float mx = e;
            for (int off = 16; off; off >>= 1) mx = fmaxf(mx, __shfl_xor_sync(FULL, mx, off));
            float ex = expf(e - mx);
            float den = ex;
            for (int off = 16; off; off >>= 1) den += __shfl_xor_sync(FULL, den, off);
            float val = (ex / den) * gf[lane * 132 + d];
            for (int off = 16; off; off >>= 1) val += __shfl_xor_sync(FULL, val, off);
            if (lane == 0) outp[(size_t)d * Ss] = val;
        }
}

// ---------------- launch ----------------
extern "C" void kernel_launch(void* const* d_in, const int* in_sizes, int n_in,
                              void* d_out, int out_size) {
    const float* xyz = (const float*)d_in[0];
    const float* pts = (const float*)d_in[1];
    const int*   tgt = (const int*)d_in[2];
    const float* w0 = (const float*)d_in[3];
    const float* b0 = (const float*)d_in[4];
    const float* g0 = (const float*)d_in[5];
    const float* be0 = (const float*)d_in[6];
    const float* m0 = (const float*)d_in[7];
    const float* v0 = (const float*)d_in[8];
    const float* w1 = (const float*)d_in[9];
    const float* b1 = (const float*)d_in[10];
    const float* g1 = (const float*)d_in[11];
    const float* be1 = (const float*)d_in[12];
    const float* m1 = (const float*)d_in[13];
    const float* v1 = (const float*)d_in[14];
    const float* w2 = (const float*)d_in[15];
    const float* b2 = (const float*)d_in[16];
    const float* g2 = (const float*)d_in[17];
    const float* be2 = (const float*)d_in[18];
    const float* m2 = (const float*)d_in[19];
    const float* v2 = (const float*)d_in[20];
    const float* a  = (const float*)d_in[21];
    float* out = (float*)d_out;

    cudaFuncSetAttribute(fps_kernel, cudaFuncAttributeMaxDynamicSharedMemorySize, 3 * Nn * 4);
    cudaFuncSetAttribute(fused_kernel, cudaFuncAttributeMaxDynamicSharedMemorySize, 17772 * 4);

    fps_kernel<<<Bb, 1024, 3 * Nn * 4>>>(xyz);
    gather_kernel<<<(Bb * Ss) / 256, 256>>>(xyz, tgt, out);
    buildF_kernel<<<Bb * (Nn / 64), 256>>>(xyz, pts);
    fold_kernel<<<64, 256>>>(w0, b0, g0, be0, m0, v0,
                             w1, b1, g1, be1, m1, v1,
                             w2, b2, g2, be2, m2, v2);
    ball_kernel<<<(Bb * Ss) / 8, 256>>>(xyz);
    fused_kernel<<<Bb * Ss, 256, 17772 * 4>>>(a, out);
}

// round 3
// speedup vs baseline: 1.0793x; 1.0793x over previous
#include <cuda_runtime.h>
#include <cuda_bf16.h>
#include <math.h>

#define Bb 8
#define Nn 8192
#define Ss 2048
#define Kk 32
#define EPSc 1e-5f
#define ALPHAc 0.2f

// ---------------- scratch (device globals; no allocations) ----------------
__device__ int   g_fps_idx[Bb * Ss];
__device__ int   g_ball_idx[Bb * Ss * Kk];
__device__ float g_newxyz[Bb * Ss * 3];
__device__ float g_F[(size_t)Bb * Nn * 64];        // 16.8 MB: [xyz(3) | points(61)] per point
__device__ float g_W0[64 * 64], g_b0[64];
__device__ float g_W1[64 * 64], g_b1[64];
__device__ float g_W2[128 * 64], g_b2[128];

// ---------------- FPS: one block per batch ----------------
__global__ void __launch_bounds__(1024) fps_kernel(const float* __restrict__ xyz) {
    extern __shared__ float smem[];
    float* xs = smem;
    float* ys = smem + Nn;
    float* zs = smem + 2 * Nn;
    __shared__ float rv[32];
    __shared__ int   ri[32];
    __shared__ int   sm_cur;

    int b = blockIdx.x;
    int tid = threadIdx.x;
    int lane = tid & 31, wid = tid >> 5;

    float px[8], py[8], pz[8], dd[8];
#pragma unroll
    for (int j = 0; j < 8; j++) {
        int i = tid + j * 1024;
        px[j] = xyz[((size_t)b * 3 + 0) * Nn + i];
        py[j] = xyz[((size_t)b * 3 + 1) * Nn + i];
        pz[j] = xyz[((size_t)b * 3 + 2) * Nn + i];
        xs[i] = px[j]; ys[i] = py[j]; zs[i] = pz[j];
        dd[j] = 1e10f;
    }
    if (tid == 0) sm_cur = 0;
    __syncthreads();

    for (int s = 0; s < Ss; s++) {
        int cur = sm_cur;
        if (tid == 0) g_fps_idx[b * Ss + s] = cur;
        float cx = xs[cur], cy = ys[cur], cz = zs[cur];

        float best = -1.0f; int bi = 0;
#pragma unroll
        for (int j = 0; j < 8; j++) {
            float dx = px[j] - cx, dy = py[j] - cy, dz = pz[j] - cz;
            float d = dx * dx + dy * dy + dz * dz;
            float nd = fminf(dd[j], d);
            dd[j] = nd;
            if (nd > best) { best = nd; bi = tid + j * 1024; }  // ascending idx -> first max
        }
#pragma unroll
        for (int off = 16; off; off >>= 1) {
            float ov = __shfl_down_sync(0xffffffffu, best, off);
            int   oi = __shfl_down_sync(0xffffffffu, bi, off);
            if (ov > best || (ov == best && oi < bi)) { best = ov; bi = oi; }
        }
        if (lane == 0) { rv[wid] = best; ri[wid] = bi; }
        __syncthreads();
        if (wid == 0) {
            best = rv[lane]; bi = ri[lane];
#pragma unroll
            for (int off = 16; off; off >>= 1) {
                float ov = __shfl_down_sync(0xffffffffu, best, off);
                int   oi = __shfl_down_sync(0xffffffffu, bi, off);
                if (ov > best || (ov == best && oi < bi)) { best = ov; bi = oi; }
            }
            if (lane == 0) sm_cur = bi;
        }
        __syncthreads();
    }
}

// ---------------- gather centers: new_xyz, new_targets ----------------
__global__ void __launch_bounds__(256) gather_kernel(const float* __restrict__ xyz,
                                                     const int* __restrict__ tgt,
                                                     float* __restrict__ out) {
    int t = blockIdx.x * 256 + threadIdx.x;   // exactly B*S threads
    int b = t >> 11, s = t & 2047;
    int i = g_fps_idx[t];
    float x = xyz[((size_t)b * 3 + 0) * Nn + i];
    float y = xyz[((size_t)b * 3 + 1) * Nn + i];
    float z = xyz[((size_t)b * 3 + 2) * Nn + i];
    g_newxyz[t * 3 + 0] = x;
    g_newxyz[t * 3 + 1] = y;
    g_newxyz[t * 3 + 2] = z;
    out[((size_t)b * 3 + 0) * Ss + s] = x;
    out[((size_t)b * 3 + 1) * Ss + s] = y;
    out[((size_t)b * 3 + 2) * Ss + s] = z;
    out[(size_t)Bb * 3 * Ss + (size_t)Bb * 128 * Ss + t] = (float)tgt[(size_t)b * Nn + i];
}

// ---------------- build F[b][n][64] = [xyz(3) | points(61)] (smem transpose) ----
__global__ void __launch_bounds__(256) buildF_kernel(const float* __restrict__ xyz,
                                                     const float* __restrict__ pts) {
    __shared__ float tile[64][65];
    int b = blockIdx.x / (Nn / 64);
    int n0 = (blockIdx.x % (Nn / 64)) * 64;
    int nl = threadIdx.x & 63;
    int cl = threadIdx.x >> 6;       // 0..3
    for (int c = cl; c < 64; c += 4) {
        int n = n0 + nl;
        float v = (c < 3) ? xyz[((size_t)b * 3 + c) * Nn + n]
                          : pts[((size_t)b * 61 + (c - 3)) * Nn + n];
        tile[c][nl] = v;
    }
    __syncthreads();
    int c = threadIdx.x & 63;
    int nb = threadIdx.x >> 6;
    for (int nn = nb; nn < 64; nn += 4)
        g_F[((size_t)(b * Nn + n0 + nn)) * 64 + c] = tile[c][nn];
}

// ---------------- fold BN into weights ----------------
__global__ void __launch_bounds__(256) fold_kernel(
    const float* w0, const float* b0, const float* g0, const float* be0, const float* m0, const float* v0,
    const float* w1, const float* b1, const float* g1, const float* be1, const float* m1, const float* v1,
    const float* w2, const float* b2, const float* g2, const float* be2, const float* m2, const float* v2) {
    int t = blockIdx.x * 256 + threadIdx.x;
    if (t < 4096) {
        int o = t >> 6;
        float sc = g0[o] / sqrtf(v0[o] + EPSc);
        g_W0[t] = w0[t] * sc;
        if ((t & 63) == 0) g_b0[o] = (b0[o] - m0[o]) * sc + be0[o];
    } else if (t < 8192) {
        int i = t - 4096; int o = i >> 6;
        float sc = g1[o] / sqrtf(v1[o] + EPSc);
        g_W1[i] = w1[i] * sc;
        if ((i & 63) == 0) g_b1[o] = (b1[o] - m1[o]) * sc + be1[o];
    } else if (t < 16384) {
        int i = t - 8192; int o = i >> 6;
        float sc = g2[o] / sqrtf(v2[o] + EPSc);
        g_W2[i] = w2[i] * sc;
        if ((i & 63) == 0) g_b2[o] = (b2[o] - m2[o]) * sc + be2[o];
    }
}

// ---------------- ball query: one warp per group, scan indices ascending ------
__global__ void __launch_bounds__(256) ball_kernel(const float* __restrict__ xyz) {
    int gw = blockIdx.x * 8 + (threadIdx.x >> 5);   // group id 0..16383
    int lane = threadIdx.x & 31;
    int b = gw >> 11;
    float cx = g_newxyz[gw * 3 + 0];
    float cy = g_newxyz[gw * 3 + 1];
    float cz = g_newxyz[gw * 3 + 2];
    const float* xb = xyz + (size_t)b * 3 * Nn;
    int cnt = 0, firstn = 0;
    for (int base = 0; base < Nn; base += 32) {
        int n = base + lane;
        float dx = xb[n] - cx, dy = xb[Nn + n] - cy, dz = xb[2 * Nn + n] - cz;
        float d = dx * dx + dy * dy + dz * dz;
        bool inb = (d <= 0.25f);
        unsigned m = __ballot_sync(0xffffffffu, inb);
        if (cnt == 0 && m) firstn = base + __ffs(m) - 1;
        int pos = cnt + __popc(m & ((1u << lane) - 1u));
        if (inb && pos < Kk) g_ball_idx[(size_t)gw * Kk + pos] = n;
        cnt += __popc(m);
        if (cnt >= Kk) break;
    }
    for (int j = cnt + lane; j < Kk; j += 32)
        g_ball_idx[(size_t)gw * Kk + j] = firstn;
}

// ============================================================================
// Fused MLP + attention. 4 groups per block, 256 threads.
// Each 64-thread team handles one group. Register tiling:
//   point  p = po + 8*pp   (po = lane&7, pp = 0..3)   -> conflict-free LDS
//   output o = og + 8*j    (og = teamlane>>3)         -> conflict-free LDS
// smem floats:
//   bufA[4*33*68]=8976  bufB[8976]  gf[4*33*132]=17424  Wsh[128*68]=8704
//   bsh[128]  dp[384]  outv[512]        total 45104 floats = 180.4 KB
// ============================================================================
#define GSTR 68
#define GROWS 2244          // 33*68
#define GFSTR 132
#define GFROWS 4356         // 33*132
#define CATROWS 4224        // 32*132

template <int COUT, int OSTR, int OROWS>
__device__ __forceinline__ void mlp_layer(const float* __restrict__ Wg,
                                          const float* __restrict__ bg,
                                          float* Wsh, float* bsh,
                                          const float* in, float* out, int tid) {
    __syncthreads();
    for (int idx = tid; idx < COUT * 64; idx += 256)
        Wsh[(idx >> 6) * 68 + (idx & 63)] = Wg[idx];
    if (tid < COUT) bsh[tid] = bg[tid];
    __syncthreads();

    constexpr int J = COUT / 8;
    int team = tid >> 6, l = tid & 63, po = l & 7, og = l >> 3;
    const float* inb = in + team * GROWS;
    float* outb = out + team * OROWS;

    float acc[4 * J];
#pragma unroll
    for (int i = 0; i < 4 * J; i++) acc[i] = 0.0f;

#pragma unroll 2
    for (int cc = 0; cc < 16; cc++) {
        float4 iv[4];
#pragma unroll
        for (int pp = 0; pp < 4; pp++)
            iv[pp] = *(const float4*)(inb + (po + 8 * pp) * GSTR + cc * 4);
#pragma unroll
        for (int j = 0; j < J; j++) {
            float4 wv = *(const float4*)(Wsh + (og + 8 * j) * 68 + cc * 4);
#pragma unroll
            for (int pp = 0; pp < 4; pp++)
                acc[pp * J + j] += iv[pp].x * wv.x + iv[pp].y * wv.y
                                 + iv[pp].z * wv.z + iv[pp].w * wv.w;
        }
    }
#pragma unroll
    for (int j = 0; j < J; j++) {
        float bv = bsh[og + 8 * j];
#pragma unroll
        for (int pp = 0; pp < 4; pp++)
            outb[(po + 8 * pp) * OSTR + og + 8 * j] = fmaxf(acc[pp * J + j] + bv, 0.0f);
    }
    // center rows (p = 32), 4 groups
    for (int idx = tid; idx < COUT * 4; idx += 256) {
        int o = idx & (COUT - 1);
        int grp = idx / COUT;
        const float* ir = in + grp * GROWS + 32 * GSTR;
        const float* wr = Wsh + o * 68;
        float s = 0.0f;
#pragma unroll 8
        for (int c = 0; c < 64; c++) s += ir[c] * wr[c];
        out[grp * OROWS + 32 * OSTR + o] = fmaxf(s + bsh[o], 0.0f);
    }
}

__global__ void __launch_bounds__(256) fused_kernel(const float* __restrict__ a_g,
                                                    float* __restrict__ d_out) {
    extern __shared__ float sm[];
    float* bufA = sm;                  // 8976
    float* bufB = sm + 8976;           // 8976
    float* gf   = sm + 17952;          // 17424
    float* Wsh  = sm + 35376;          // 8704
    float* bsh  = sm + 44080;          // 128
    float* dpx  = sm + 44208;          // 128
    float* dpy  = sm + 44336;          // 128
    float* dpz  = sm + 44464;          // 128
    float* outv = sm + 44592;          // 512

    int tid = threadIdx.x;
    int w = tid >> 5, lane = tid & 31;
    int g0 = blockIdx.x * 4;
    int bB = g0 >> 11;                  // all 4 groups share a batch (s0 % 4 == 0)

    // ---- load 4*33 feature rows ----
#pragma unroll
    for (int grp = 0; grp < 4; grp++) {
        int g = g0 + grp;
        for (int p = w; p < 33; p += 8) {
            int src = (p < 32) ? g_ball_idx[(size_t)g * Kk + p] : g_fps_idx[g];
            float2 v = ((const float2*)(g_F + (size_t)(bB * Nn + src) * 64))[lane];
            bufA[grp * GROWS + p * GSTR + lane * 2]     = v.x;
            bufA[grp * GROWS + p * GSTR + lane * 2 + 1] = v.y;
        }
    }
    __syncthreads();
    if (tid < 128) {
        int grp = tid >> 5, k = tid & 31;
        int g = g0 + grp;
        float nx = g_newxyz[g * 3 + 0];
        float ny = g_newxyz[g * 3 + 1];
        float nz = g_newxyz[g * 3 + 2];
        float* row = bufA + grp * GROWS + k * GSTR;
        float gx = row[0], gy = row[1], gz = row[2];
        row[0] = gx - nx; row[1] = gy - ny; row[2] = gz - nz;   // grouped_norm
        dpx[grp * 32 + k] = nx - gx;                            // delta_p
        dpy[grp * 32 + k] = ny - gy;
        dpz[grp * 32 + k] = nz - gz;
    }

    // ---- 3-layer MLP ----
    mlp_layer<64, GSTR, GROWS>(g_W0, g_b0, Wsh, bsh, bufA, bufB, tid);
    mlp_layer<64, GSTR, GROWS>(g_W1, g_b1, Wsh, bsh, bufB, bufA, tid);
    mlp_layer<128, GFSTR, GFROWS>(g_W2, g_b2, Wsh, bsh, bufA, gf, tid);
    __syncthreads();

    // ---- build cat[4][32][132] = [delta_p(3) | cf - gf (128) | 0] in bufA+bufB ----
    float* cat = bufA;
    for (int idx = tid; idx < 4 * 32 * 131; idx += 256) {
        int grp = idx / (32 * 131);
        int r = idx - grp * (32 * 131);
        int k = r / 131;
        int c = r - k * 131;
        const float* gfb = gf + grp * GFROWS;
        float v;
        if (c == 0)      v = dpx[grp * 32 + k];
        else if (c == 1) v = dpy[grp * 32 + k];
        else if (c == 2) v = dpz[grp * 32 + k];
        else             v = gfb[32 * GFSTR + (c - 3)] - gfb[k * GFSTR + (c - 3)];
        cat[grp * CATROWS + k * GFSTR + c] = v;
    }
    if (tid < 128) cat[(tid >> 5) * CATROWS + (tid & 31) * GFSTR + 131] = 0.0f;

    // ---- e = cat @ a  (131 -> 128): 4pt x 16out register tile ----
    int team = tid >> 6, l = tid & 63, po = l & 7, og = l >> 3;
    const float* catb = cat + team * CATROWS;
    float acc[64];
#pragma unroll
    for (int i = 0; i < 64; i++) acc[i] = 0.0f;

    for (int t = 0; t < 3; t++) {
        int c0 = t * 64;
        int tw = (t < 2) ? 64 : 4;
        __syncthreads();
        for (int idx = tid; idx < 128 * tw; idx += 256) {
            int d = idx & 127, cc = idx >> 7;
            int c = c0 + cc;
            Wsh[d * 68 + cc] = (c < 131) ? a_g[(size_t)c * 128 + d] : 0.0f;
        }
        __syncthreads();
        int nch = tw >> 2;
#pragma unroll 2
        for (int cc = 0; cc < nch; cc++) {
            float4 iv[4];
#pragma unroll
            for (int pp = 0; pp < 4; pp++)
                iv[pp] = *(const float4*)(catb + (po + 8 * pp) * GFSTR + c0 + cc * 4);
#pragma unroll
            for (int j = 0; j < 16; j++) {
                float4 wv = *(const float4*)(Wsh + (og + 8 * j) * 68 + cc * 4);
#pragma unroll
                for (int pp = 0; pp < 4; pp++)
                    acc[pp * 16 + j] += iv[pp].x * wv.x + iv[pp].y * wv.y
                                      + iv[pp].z * wv.z + iv[pp].w * wv.w;
            }
        }
    }

    // ---- leaky relu + softmax over k (8-lane xor subgroups + 4 regs) ----
    const unsigned FULL = 0xffffffffu;
    const float* gfb = gf + team * GFROWS;
#pragma unroll
    for (int j = 0; j < 16; j++) {
        int d = og + 8 * j;
        float e[4], mx = -1e30f;
#pragma unroll
        for (int pp = 0; pp < 4; pp++) {
            float v = acc[pp * 16 + j];
            v = (v >= 0.0f) ? v : (ALPHAc * v);
            e[pp] = v;
            mx = fmaxf(mx, v);
        }
        mx = fmaxf(mx, __shfl_xor_sync(FULL, mx, 1));
        mx = fmaxf(mx, __shfl_xor_sync(FULL, mx, 2));
        mx = fmaxf(mx, __shfl_xor_sync(FULL, mx, 4));
        float den = 0.0f, ex[4];
#pragma unroll
        for (int pp = 0; pp < 4; pp++) { ex[pp] = expf(e[pp] - mx); den += ex[pp]; }
        den += __shfl_xor_sync(FULL, den, 1);
        den += __shfl_xor_sync(FULL, den, 2);
        den += __shfl_xor_sync(FULL, den, 4);
        float rd = 1.0f / den;
        float val = 0.0f;
#pragma unroll
        for (int pp = 0; pp < 4; pp++)
            val += ex[pp] * rd * gfb[(po + 8 * pp) * GFSTR + d];
        val += __shfl_xor_sync(FULL, val, 1);
        val += __shfl_xor_sync(FULL, val, 2);
        val += __shfl_xor_sync(FULL, val, 4);
        if (po == 0) outv[d * 4 + team] = val;
    }
    __syncthreads();

    // ---- coalesced output: 4 consecutive s per d ----
    if (tid < 128) {
        float4 v = *(const float4*)(outv + tid * 4);
        int s0 = g0 & 2047;
        *(float4*)(d_out + (size_t)Bb * 3 * Ss + (size_t)bB * 128 * Ss
                   + (size_t)tid * Ss + s0) = v;
    }
}

// ---------------- launch ----------------
extern "C" void kernel_launch(void* const* d_in, const int* in_sizes, int n_in,
                              void* d_out, int out_size) {
    const float* xyz = (const float*)d_in[0];
    const float* pts = (const float*)d_in[1];
    const int*   tgt = (const int*)d_in[2];
    const float* w0 = (const float*)d_in[3];
    const float* b0 = (const float*)d_in[4];
    const float* g0 = (const float*)d_in[5];
    const float* be0 = (const float*)d_in[6];
    const float* m0 = (const float*)d_in[7];
    const float* v0 = (const float*)d_in[8];
    const float* w1 = (const float*)d_in[9];
    const float* b1 = (const float*)d_in[10];
    const float* g1 = (const float*)d_in[11];
    const float* be1 = (const float*)d_in[12];
    const float* m1 = (const float*)d_in[13];
    const float* v1 = (const float*)d_in[14];
    const float* w2 = (const float*)d_in[15];
    const float* b2 = (const float*)d_in[16];
    const float* g2 = (const float*)d_in[17];
    const float* be2 = (const float*)d_in[18];
    const float* m2 = (const float*)d_in[19];
    const float* v2 = (const float*)d_in[20];
    const float* a  = (const float*)d_in[21];
    float* out = (float*)d_out;

    cudaFuncSetAttribute(fps_kernel, cudaFuncAttributeMaxDynamicSharedMemorySize, 3 * Nn * 4);
    cudaFuncSetAttribute(fused_kernel, cudaFuncAttributeMaxDynamicSharedMemorySize, 45104 * 4);

    fps_kernel<<<Bb, 1024, 3 * Nn * 4>>>(xyz);
    gather_kernel<<<(Bb * Ss) / 256, 256>>>(xyz, tgt, out);
    buildF_kernel<<<Bb * (Nn / 64), 256>>>(xyz, pts);
    fold_kernel<<<64, 256>>>(w0, b0, g0, be0, m0, v0,
                             w1, b1, g1, be1, m1, v1,
                             w2, b2, g2, be2, m2, v2);
    ball_kernel<<<(Bb * Ss) / 8, 256>>>(xyz);
    fused_kernel<<<Bb * Ss / 4, 256, 45104 * 4>>>(a, out);
}

// round 4
// speedup vs baseline: 1.1592x; 1.0740x over previous
#include <cuda_runtime.h>
#include <cuda_bf16.h>
#include <math.h>

#define Bb 8
#define Nn 8192
#define Ss 2048
#define Kk 32
#define EPSc 1e-5f
#define ALPHAc 0.2f

// ---- packed f32x2 helpers (Blackwell) ----
#define PACKX2(out, lo, hi) \
    asm("mov.b64 %0, {%1, %2};" : "=l"(out) : "f"(lo), "f"(hi))
#define UNPACKX2(lo, hi, in) \
    asm("mov.b64 {%0, %1}, %2;" : "=f"(lo), "=f"(hi) : "l"(in))
#define ADDX2(d, a, b) \
    asm("add.rn.f32x2 %0, %1, %2;" : "=l"(d) : "l"(a), "l"(b))
#define MULX2(d, a, b) \
    asm("mul.rn.f32x2 %0, %1, %2;" : "=l"(d) : "l"(a), "l"(b))
#define FMAX2(d, a, b, c) \
    asm("fma.rn.f32x2 %0, %1, %2, %3;" : "=l"(d) : "l"(a), "l"(b), "l"(c))

// ---------------- scratch (device globals; no allocations) ----------------
__device__ int   g_fps_idx[Bb * Ss];
__device__ int   g_ball_idx[Bb * Ss * Kk];
__device__ float g_newxyz[Bb * Ss * 3];
__device__ float g_F[(size_t)Bb * Nn * 64];        // [xyz(3) | points(61)] per point
__device__ float g_W0[64 * 64], g_b0[64];
__device__ float g_W1[64 * 64], g_b1[64];
__device__ float g_W2[128 * 64], g_b2[128];

// ---------------- FPS: one block per batch, 1 barrier/step ----------------
__global__ void __launch_bounds__(1024) fps_kernel(const float* __restrict__ xyz) {
    extern __shared__ float4 pts4[];                 // 8192 float4 = 128 KB
    __shared__ float rv[2][32];
    __shared__ int   ri[2][32];

    int b = blockIdx.x;
    int tid = threadIdx.x;
    int lane = tid & 31, wid = tid >> 5;
    const unsigned FULL = 0xffffffffu;

    float xr[8], yr[8], zr[8], dd[8];
    unsigned long long px2[4], py2[4], pz2[4];
#pragma unroll
    for (int j = 0; j < 8; j++) {
        int i = tid + j * 1024;
        xr[j] = xyz[((size_t)b * 3 + 0) * Nn + i];
        yr[j] = xyz[((size_t)b * 3 + 1) * Nn + i];
        zr[j] = xyz[((size_t)b * 3 + 2) * Nn + i];
        pts4[i] = make_float4(xr[j], yr[j], zr[j], 0.0f);
        dd[j] = 1e10f;
    }
#pragma unroll
    for (int m = 0; m < 4; m++) {
        PACKX2(px2[m], xr[2 * m], xr[2 * m + 1]);
        PACKX2(py2[m], yr[2 * m], yr[2 * m + 1]);
        PACKX2(pz2[m], zr[2 * m], zr[2 * m + 1]);
    }
    __syncthreads();

    int cur = 0;
    for (int s = 0; s < Ss; s++) {
        if (tid == 0) g_fps_idx[b * Ss + s] = cur;
        float4 c = pts4[cur];
        float ncx = -c.x, ncy = -c.y, ncz = -c.z;
        unsigned long long cx2, cy2, cz2;
        PACKX2(cx2, ncx, ncx);
        PACKX2(cy2, ncy, ncy);
        PACKX2(cz2, ncz, ncz);

        float best = -1.0f; int bi = 0;
#pragma unroll
        for (int m = 0; m < 4; m++) {
            unsigned long long dx2, dy2, dz2, t2;
            ADDX2(dx2, px2[m], cx2);
            ADDX2(dy2, py2[m], cy2);
            ADDX2(dz2, pz2[m], cz2);
            MULX2(t2, dx2, dx2);
            FMAX2(t2, dy2, dy2, t2);
            FMAX2(t2, dz2, dz2, t2);
            float dl, dh;
            UNPACKX2(dl, dh, t2);
            float n0 = fminf(dd[2 * m], dl);     dd[2 * m] = n0;
            float n1 = fminf(dd[2 * m + 1], dh); dd[2 * m + 1] = n1;
            if (n0 > best) { best = n0; bi = tid + (2 * m) * 1024; }
            if (n1 > best) { best = n1; bi = tid + (2 * m + 1) * 1024; }
        }
        // warp xor-reduce: all lanes converge, ties -> smallest idx
#pragma unroll
        for (int off = 16; off; off >>= 1) {
            float ov = __shfl_xor_sync(FULL, best, off);
            int   oi = __shfl_xor_sync(FULL, bi, off);
            if (ov > best || (ov == best && oi < bi)) { best = ov; bi = oi; }
        }
        int par = s & 1;
        if (lane == 0) { rv[par][wid] = best; ri[par][wid] = bi; }
        __syncthreads();
        float v = rv[par][lane];
        int  ii = ri[par][lane];
#pragma unroll
        for (int off = 16; off; off >>= 1) {
            float ov = __shfl_xor_sync(FULL, v, off);
            int   oi = __shfl_xor_sync(FULL, ii, off);
            if (ov > v || (ov == v && oi < ii)) { v = ov; ii = oi; }
        }
        cur = ii;       // every thread agrees
    }
}

// ---------------- gather centers: new_xyz, new_targets ----------------
__global__ void __launch_bounds__(256) gather_kernel(const float* __restrict__ xyz,
                                                     const int* __restrict__ tgt,
                                                     float* __restrict__ out) {
    int t = blockIdx.x * 256 + threadIdx.x;   // exactly B*S threads
    int b = t >> 11, s = t & 2047;
    int i = g_fps_idx[t];
    float x = xyz[((size_t)b * 3 + 0) * Nn + i];
    float y = xyz[((size_t)b * 3 + 1) * Nn + i];
    float z = xyz[((size_t)b * 3 + 2) * Nn + i];
    g_newxyz[t * 3 + 0] = x;
    g_newxyz[t * 3 + 1] = y;
    g_newxyz[t * 3 + 2] = z;
    out[((size_t)b * 3 + 0) * Ss + s] = x;
    out[((size_t)b * 3 + 1) * Ss + s] = y;
    out[((size_t)b * 3 + 2) * Ss + s] = z;
    out[(size_t)Bb * 3 * Ss + (size_t)Bb * 128 * Ss + t] = (float)tgt[(size_t)b * Nn + i];
}

// ---------------- build F[b][n][64] = [xyz(3) | points(61)] ----------------
__global__ void __launch_bounds__(256) buildF_kernel(const float* __restrict__ xyz,
                                                     const float* __restrict__ pts) {
    __shared__ float tile[64][65];
    int b = blockIdx.x / (Nn / 64);
    int n0 = (blockIdx.x % (Nn / 64)) * 64;
    int nl = threadIdx.x & 63;
    int cl = threadIdx.x >> 6;
    for (int c = cl; c < 64; c += 4) {
        int n = n0 + nl;
        float v = (c < 3) ? xyz[((size_t)b * 3 + c) * Nn + n]
                          : pts[((size_t)b * 61 + (c - 3)) * Nn + n];
        tile[c][nl] = v;
    }
    __syncthreads();
    int c = threadIdx.x & 63;
    int nb = threadIdx.x >> 6;
    for (int nn = nb; nn < 64; nn += 4)
        g_F[((size_t)(b * Nn + n0 + nn)) * 64 + c] = tile[c][nn];
}

// ---------------- fold BN into weights (split for ncu slotting) ----------------
__global__ void __launch_bounds__(256) fold01_kernel(
    const float* w0, const float* b0, const float* g0, const float* be0, const float* m0, const float* v0,
    const float* w1, const float* b1, const float* g1, const float* be1, const float* m1, const float* v1) {
    int t = blockIdx.x * 256 + threadIdx.x;
    if (t < 4096) {
        int o = t >> 6;
        float sc = g0[o] / sqrtf(v0[o] + EPSc);
        g_W0[t] = w0[t] * sc;
        if ((t & 63) == 0) g_b0[o] = (b0[o] - m0[o]) * sc + be0[o];
    } else if (t < 8192) {
        int i = t - 4096; int o = i >> 6;
        float sc = g1[o] / sqrtf(v1[o] + EPSc);
        g_W1[i] = w1[i] * sc;
        if ((i & 63) == 0) g_b1[o] = (b1[o] - m1[o]) * sc + be1[o];
    }
}
__global__ void __launch_bounds__(256) fold2_kernel(
    const float* w2, const float* b2, const float* g2, const float* be2, const float* m2, const float* v2) {
    int i = blockIdx.x * 256 + threadIdx.x;
    if (i < 8192) {
        int o = i >> 6;
        float sc = g2[o] / sqrtf(v2[o] + EPSc);
        g_W2[i] = w2[i] * sc;
        if ((i & 63) == 0) g_b2[o] = (b2[o] - m2[o]) * sc + be2[o];
    }
}

// ---------------- ball query: one warp per group ----------------
__global__ void __launch_bounds__(256) ball_kernel(const float* __restrict__ xyz) {
    int gw = blockIdx.x * 8 + (threadIdx.x >> 5);
    int lane = threadIdx.x & 31;
    int b = gw >> 11;
    float cx = g_newxyz[gw * 3 + 0];
    float cy = g_newxyz[gw * 3 + 1];
    float cz = g_newxyz[gw * 3 + 2];
    const float* xb = xyz + (size_t)b * 3 * Nn;
    int cnt = 0, firstn = 0;
    for (int base = 0; base < Nn; base += 32) {
        int n = base + lane;
        float dx = xb[n] - cx, dy = xb[Nn + n] - cy, dz = xb[2 * Nn + n] - cz;
        float d = dx * dx + dy * dy + dz * dz;
        bool inb = (d <= 0.25f);
        unsigned m = __ballot_sync(0xffffffffu, inb);
        if (cnt == 0 && m) firstn = base + __ffs(m) - 1;
        int pos = cnt + __popc(m & ((1u << lane) - 1u));
        if (inb && pos < Kk) g_ball_idx[(size_t)gw * Kk + pos] = n;
        cnt += __popc(m);
        if (cnt >= Kk) break;
    }
    for (int j = cnt + lane; j < Kk; j += 32)
        g_ball_idx[(size_t)gw * Kk + j] = firstn;
}

// ============================================================================
// Fused MLP + attention. 2 groups per block, 256 threads (128-thread teams),
// 108 KB smem -> 2 CTAs/SM so barrier/fill phases of one CTA overlap the
// other's FFMA work.
//   point  p = po + 8*pp   (po = l&7)    -> conflict-free LDS (stride 272 B)
//   output o = og + 16*j   (og = l>>3, 0..15)
// ============================================================================
#define GSTR 68
#define GROWS 2244          // 33*68
#define GFSTR 132
#define GFROWS 4356         // 33*132
#define CATROWS 4224        // 32*132
// smem floats: bufA[2*2244]=4488 bufB=4488 gf[2*4356]=8712 Wsh[128*68]=8704
//              bsh[128] dp[192] outv[256]  total=26968 fl = 107872 B

template <int COUT, int OSTR, int OROWS>
__device__ __forceinline__ void mlp_layer(const float* __restrict__ Wg,
                                          const float* __restrict__ bg,
                                          float* Wsh, float* bsh,
                                          const float* in, float* out, int tid) {
    __syncthreads();
    for (int idx = tid; idx < COUT * 64; idx += 256)
        Wsh[(idx >> 6) * 68 + (idx & 63)] = Wg[idx];
    if (tid < COUT) bsh[tid] = bg[tid];
    __syncthreads();

    constexpr int J = COUT / 16;
    int team = tid >> 7, l = tid & 127, po = l & 7, og = l >> 3;   // og 0..15
    const float* inb = in + team * GROWS;
    float* outb = out + team * OROWS;

    float acc[4 * J];
#pragma unroll
    for (int i = 0; i < 4 * J; i++) acc[i] = 0.0f;

#pragma unroll 2
    for (int cc = 0; cc < 16; cc++) {
        float4 iv[4];
#pragma unroll
        for (int pp = 0; pp < 4; pp++)
            iv[pp] = *(const float4*)(inb + (po + 8 * pp) * GSTR + cc * 4);
#pragma unroll
        for (int j = 0; j < J; j++) {
            float4 wv = *(const float4*)(Wsh + (og + 16 * j) * 68 + cc * 4);
#pragma unroll
            for (int pp = 0; pp < 4; pp++)
                acc[pp * J + j] += iv[pp].x * wv.x + iv[pp].y * wv.y
                                 + iv[pp].z * wv.z + iv[pp].w * wv.w;
        }
    }
#pragma unroll
    for (int j = 0; j < J; j++) {
        float bv = bsh[og + 16 * j];
#pragma unroll
        for (int pp = 0; pp < 4; pp++)
            outb[(po + 8 * pp) * OSTR + og + 16 * j] = fmaxf(acc[pp * J + j] + bv, 0.0f);
    }
    // center rows (p = 32), 2 groups, float4 dots
    for (int idx = tid; idx < COUT * 2; idx += 256) {
        int o = idx & (COUT - 1);
        int grp = idx / COUT;
        const float* ir = in + grp * GROWS + 32 * GSTR;
        const float* wr = Wsh + o * 68;
        float s = 0.0f;
#pragma unroll
        for (int c = 0; c < 16; c++) {
            float4 a4 = *(const float4*)(ir + c * 4);
            float4 w4 = *(const float4*)(wr + c * 4);
            s += a4.x * w4.x + a4.y * w4.y + a4.z * w4.z + a4.w * w4.w;
        }
        out[grp * OROWS + 32 * OSTR + o] = fmaxf(s + bsh[o], 0.0f);
    }
}

__global__ void __launch_bounds__(256) fused_kernel(const float* __restrict__ a_g,
                                                    float* __restrict__ d_out) {
    extern __shared__ float sm[];
    float* bufA = sm;                  // 4488
    float* bufB = sm + 4488;           // 4488
    float* gf   = sm + 8976;           // 8712
    float* Wsh  = sm + 17688;          // 8704
    float* bsh  = sm + 26392;          // 128
    float* dpx  = sm + 26520;          // 64
    float* dpy  = sm + 26584;          // 64
    float* dpz  = sm + 26648;          // 64
    float* outv = sm + 26712;          // 256

    int tid = threadIdx.x;
    int w = tid >> 5, lane = tid & 31;
    int g0 = blockIdx.x * 2;
    int bB = g0 >> 11;

    // ---- load 2*33 feature rows ----
#pragma unroll
    for (int grp = 0; grp < 2; grp++) {
        int g = g0 + grp;
        for (int p = w; p < 33; p += 8) {
            int src = (p < 32) ? g_ball_idx[(size_t)g * Kk + p] : g_fps_idx[g];
            float2 v = ((const float2*)(g_F + (size_t)(bB * Nn + src) * 64))[lane];
            bufA[grp * GROWS + p * GSTR + lane * 2]     = v.x;
            bufA[grp * GROWS + p * GSTR + lane * 2 + 1] = v.y;
        }
    }
    __syncthreads();
    if (tid < 64) {
        int grp = tid >> 5, k = tid & 31;
        int g = g0 + grp;
        float nx = g_newxyz[g * 3 + 0];
        float ny = g_newxyz[g * 3 + 1];
        float nz = g_newxyz[g * 3 + 2];
        float* row = bufA + grp * GROWS + k * GSTR;
        float gx = row[0], gy = row[1], gz = row[2];
        row[0] = gx - nx; row[1] = gy - ny; row[2] = gz - nz;   // grouped_norm
        dpx[grp * 32 + k] = nx - gx;                            // delta_p
        dpy[grp * 32 + k] = ny - gy;
        dpz[grp * 32 + k] = nz - gz;
    }

    // ---- 3-layer MLP ----
    mlp_layer<64, GSTR, GROWS>(g_W0, g_b0, Wsh, bsh, bufA, bufB, tid);
    mlp_layer<64, GSTR, GROWS>(g_W1, g_b1, Wsh, bsh, bufB, bufA, tid);
    mlp_layer<128, GFSTR, GFROWS>(g_W2, g_b2, Wsh, bsh, bufA, gf, tid);
    __syncthreads();

    // ---- build cat[2][32][132] = [delta_p(3) | cf - gf (128) | 0] ----
    float* cat = bufA;      // bufA+bufB contiguous: 8976 >= 2*4224
    for (int idx = tid; idx < 2 * 32 * 131; idx += 256) {
        int grp = idx / (32 * 131);
        int r = idx - grp * (32 * 131);
        int k = r / 131;
        int c = r - k * 131;
        const float* gfb = gf + grp * GFROWS;
        float v;
        if (c == 0)      v = dpx[grp * 32 + k];
        else if (c == 1) v = dpy[grp * 32 + k];
        else if (c == 2) v = dpz[grp * 32 + k];
        else             v = gfb[32 * GFSTR + (c - 3)] - gfb[k * GFSTR + (c - 3)];
        cat[grp * CATROWS + k * GFSTR + c] = v;
    }
    if (tid < 64) cat[(tid >> 5) * CATROWS + (tid & 31) * GFSTR + 131] = 0.0f;

    // ---- e = cat @ a  (131 -> 128): 4pt x 8out register tile per thread ----
    int team = tid >> 7, l = tid & 127, po = l & 7, og = l >> 3;   // og 0..15
    const float* catb = cat + team * CATROWS;
    float acc[32];
#pragma unroll
    for (int i = 0; i < 32; i++) acc[i] = 0.0f;

    for (int t = 0; t < 3; t++) {
        int c0 = t * 64;
        int tw = (t < 2) ? 64 : 4;
        __syncthreads();
        for (int idx = tid; idx < 128 * tw; idx += 256) {
            int d = idx & 127, cc = idx >> 7;
            int c = c0 + cc;
            Wsh[d * 68 + cc] = (c < 131) ? a_g[(size_t)c * 128 + d] : 0.0f;
        }
        __syncthreads();
        int nch = tw >> 2;
#pragma unroll 2
        for (int cc = 0; cc < nch; cc++) {
            float4 iv[4];
#pragma unroll
            for (int pp = 0; pp < 4; pp++)
                iv[pp] = *(const float4*)(catb + (po + 8 * pp) * GFSTR + c0 + cc * 4);
#pragma unroll
            for (int j = 0; j < 8; j++) {
                float4 wv = *(const float4*)(Wsh + (og + 16 * j) * 68 + cc * 4);
#pragma unroll
                for (int pp = 0; pp < 4; pp++)
                    acc[pp * 8 + j] += iv[pp].x * wv.x + iv[pp].y * wv.y
                                     + iv[pp].z * wv.z + iv[pp].w * wv.w;
            }
        }
    }

    // ---- leaky relu + softmax over k (8-lane xor subgroups + 4 regs) ----
    const unsigned FULL = 0xffffffffu;
    const float* gfb = gf + team * GFROWS;
#pragma unroll
    for (int j = 0; j < 8; j++) {
        int d = og + 16 * j;
        float e[4], mx = -1e30f;
#pragma unroll
        for (int pp = 0; pp < 4; pp++) {
            float v = acc[pp * 8 + j];
            v = (v >= 0.0f) ? v : (ALPHAc * v);
            e[pp] = v;
            mx = fmaxf(mx, v);
        }
        mx = fmaxf(mx, __shfl_xor_sync(FULL, mx, 1));
        mx = fmaxf(mx, __shfl_xor_sync(FULL, mx, 2));
        mx = fmaxf(mx, __shfl_xor_sync(FULL, mx, 4));
        float den = 0.0f, ex[4];
#pragma unroll
        for (int pp = 0; pp < 4; pp++) { ex[pp] = expf(e[pp] - mx); den += ex[pp]; }
        den += __shfl_xor_sync(FULL, den, 1);
        den += __shfl_xor_sync(FULL, den, 2);
        den += __shfl_xor_sync(FULL, den, 4);
        float rd = 1.0f / den;
        float val = 0.0f;
#pragma unroll
        for (int pp = 0; pp < 4; pp++)
            val += ex[pp] * rd * gfb[(po + 8 * pp) * GFSTR + d];
        val += __shfl_xor_sync(FULL, val, 1);
        val += __shfl_xor_sync(FULL, val, 2);
        val += __shfl_xor_sync(FULL, val, 4);
        if (po == 0) outv[d * 2 + team] = val;
    }
    __syncthreads();

    // ---- coalesced output: 2 consecutive s per d ----
    if (tid < 128) {
        float2 v = *(const float2*)(outv + tid * 2);
        int s0 = g0 & 2047;
        *(float2*)(d_out + (size_t)Bb * 3 * Ss + (size_t)bB * 128 * Ss
                   + (size_t)tid * Ss + s0) = v;
    }
}

// ---------------- launch ----------------
extern "C" void kernel_launch(void* const* d_in, const int* in_sizes, int n_in,
                              void* d_out, int out_size) {
    const float* xyz = (const float*)d_in[0];
    const float* pts = (const float*)d_in[1];
    const int*   tgt = (const int*)d_in[2];
    const float* w0 = (const float*)d_in[3];
    const float* b0 = (const float*)d_in[4];
    const float* g0 = (const float*)d_in[5];
    const float* be0 = (const float*)d_in[6];
    const float* m0 = (const float*)d_in[7];
    const float* v0 = (const float*)d_in[8];
    const float* w1 = (const float*)d_in[9];
    const float* b1 = (const float*)d_in[10];
    const float* g1 = (const float*)d_in[11];
    const float* be1 = (const float*)d_in[12];
    const float* m1 = (const float*)d_in[13];
    const float* v1 = (const float*)d_in[14];
    const float* w2 = (const float*)d_in[15];
    const float* b2 = (const float*)d_in[16];
    const float* g2 = (const float*)d_in[17];
    const float* be2 = (const float*)d_in[18];
    const float* m2 = (const float*)d_in[19];
    const float* v2 = (const float*)d_in[20];
    const float* a  = (const float*)d_in[21];
    float* out = (float*)d_out;

    cudaFuncSetAttribute(fps_kernel, cudaFuncAttributeMaxDynamicSharedMemorySize, Nn * 16);
    cudaFuncSetAttribute(fused_kernel, cudaFuncAttributeMaxDynamicSharedMemorySize, 26968 * 4);

    // order chosen so the ncu capture slot (4th launch) lands on fps_kernel
    buildF_kernel<<<Bb * (Nn / 64), 256>>>(xyz, pts);
    fold01_kernel<<<32, 256>>>(w0, b0, g0, be0, m0, v0,
                               w1, b1, g1, be1, m1, v1);
    fold2_kernel<<<32, 256>>>(w2, b2, g2, be2, m2, v2);
    fps_kernel<<<Bb, 1024, Nn * 16>>>(xyz);
    gather_kernel<<<(Bb * Ss) / 256, 256>>>(xyz, tgt, out);
    ball_kernel<<<(Bb * Ss) / 8, 256>>>(xyz);
    fused_kernel<<<Bb * Ss / 2, 256, 26968 * 4>>>(a, out);
}

// round 5
// speedup vs baseline: 1.2381x; 1.0681x over previous
#include <cuda_runtime.h>
#include <cuda_bf16.h>
#include <math.h>

#define Bb 8
#define Nn 8192
#define Ss 2048
#define Kk 32
#define EPSc 1e-5f
#define ALPHAc 0.2f

typedef unsigned long long u64;

// ---- packed f32x2 helpers (Blackwell) ----
#define PACKX2(out, lo, hi) \
    asm("mov.b64 %0, {%1, %2};" : "=l"(out) : "f"(lo), "f"(hi))
#define UNPACKX2(lo, hi, in) \
    asm("mov.b64 {%0, %1}, %2;" : "=f"(lo), "=f"(hi) : "l"(in))
#define ADDX2(d, a, b) \
    asm("add.rn.f32x2 %0, %1, %2;" : "=l"(d) : "l"(a), "l"(b))
#define MULX2(d, a, b) \
    asm("mul.rn.f32x2 %0, %1, %2;" : "=l"(d) : "l"(a), "l"(b))
#define FMAX2(d, a, b, c) \
    asm("fma.rn.f32x2 %0, %1, %2, %3;" : "=l"(d) : "l"(a), "l"(b), "l"(c))

// ---------------- scratch (device globals; no allocations) ----------------
__device__ int   g_fps_idx[Bb * Ss];
__device__ int   g_ball_idx[Bb * Ss * Kk];
__device__ float g_newxyz[Bb * Ss * 3];
__device__ __align__(16) float g_F[(size_t)Bb * Nn * 64];   // [xyz(3)|points(61)]
// interleaved weights: Wp[pair][c][2], row pad 136 floats
__device__ __align__(16) float g_W0p[32 * 136];
__device__ __align__(16) float g_W1p[32 * 136];
__device__ __align__(16) float g_W2p[64 * 136];
__device__ __align__(16) float g_Ap[3 * 8704];               // a interleaved, 3 c-tiles
__device__ float g_b0[64], g_b1[64], g_b2[128];

// ---------------- FPS: one block per batch, 1 barrier/step ----------------
__global__ void __launch_bounds__(1024) fps_kernel(const float* __restrict__ xyz) {
    extern __shared__ float4 pts4[];                 // 8192 float4 = 128 KB
    __shared__ float rv[2][32];
    __shared__ int   ri[2][32];

    int b = blockIdx.x;
    int tid = threadIdx.x;
    int lane = tid & 31, wid = tid >> 5;
    const unsigned FULL = 0xffffffffu;

    float xr[8], yr[8], zr[8], dd[8];
    u64 px2[4], py2[4], pz2[4];
#pragma unroll
    for (int j = 0; j < 8; j++) {
        int i = tid + j * 1024;
        xr[j] = xyz[((size_t)b * 3 + 0) * Nn + i];
        yr[j] = xyz[((size_t)b * 3 + 1) * Nn + i];
        zr[j] = xyz[((size_t)b * 3 + 2) * Nn + i];
        pts4[i] = make_float4(xr[j], yr[j], zr[j], 0.0f);
        dd[j] = 1e10f;
    }
#pragma unroll
    for (int m = 0; m < 4; m++) {
        PACKX2(px2[m], xr[2 * m], xr[2 * m + 1]);
        PACKX2(py2[m], yr[2 * m], yr[2 * m + 1]);
        PACKX2(pz2[m], zr[2 * m], zr[2 * m + 1]);
    }
    __syncthreads();

    int cur = 0;
    for (int s = 0; s < Ss; s++) {
        if (tid == 0) g_fps_idx[b * Ss + s] = cur;
        float4 c = pts4[cur];
        float ncx = -c.x, ncy = -c.y, ncz = -c.z;
        u64 cx2, cy2, cz2;
        PACKX2(cx2, ncx, ncx);
        PACKX2(cy2, ncy, ncy);
        PACKX2(cz2, ncz, ncz);

        float best = -1.0f; int bi = 0;
#pragma unroll
        for (int m = 0; m < 4; m++) {
            u64 dx2, dy2, dz2, t2;
            ADDX2(dx2, px2[m], cx2);
            ADDX2(dy2, py2[m], cy2);
            ADDX2(dz2, pz2[m], cz2);
            MULX2(t2, dx2, dx2);
            FMAX2(t2, dy2, dy2, t2);
            FMAX2(t2, dz2, dz2, t2);
            float dl, dh;
            UNPACKX2(dl, dh, t2);
            float n0 = fminf(dd[2 * m], dl);     dd[2 * m] = n0;
            float n1 = fminf(dd[2 * m + 1], dh); dd[2 * m + 1] = n1;
            if (n0 > best) { best = n0; bi = tid + (2 * m) * 1024; }
            if (n1 > best) { best = n1; bi = tid + (2 * m + 1) * 1024; }
        }
#pragma unroll
        for (int off = 16; off; off >>= 1) {
            float ov = __shfl_xor_sync(FULL, best, off);
            int   oi = __shfl_xor_sync(FULL, bi, off);
            if (ov > best || (ov == best && oi < bi)) { best = ov; bi = oi; }
        }
        int par = s & 1;
        if (lane == 0) { rv[par][wid] = best; ri[par][wid] = bi; }
        __syncthreads();
        float v = rv[par][lane];
        int  ii = ri[par][lane];
#pragma unroll
        for (int off = 16; off; off >>= 1) {
            float ov = __shfl_xor_sync(FULL, v, off);
            int   oi = __shfl_xor_sync(FULL, ii, off);
            if (ov > v || (ov == v && oi < ii)) { v = ov; ii = oi; }
        }
        cur = ii;
    }
}

// ---------------- prep: buildF + fold01 + fold2 + a-interleave ----------------
__global__ void __launch_bounds__(256) prep_kernel(
    const float* __restrict__ xyz, const float* __restrict__ pts,
    const float* w0, const float* b0, const float* g0, const float* be0, const float* m0, const float* v0,
    const float* w1, const float* b1, const float* g1, const float* be1, const float* m1, const float* v1,
    const float* w2, const float* b2, const float* g2, const float* be2, const float* m2, const float* v2,
    const float* __restrict__ a) {
    __shared__ float tile[64][65];
    int blk = blockIdx.x;
    int tid = threadIdx.x;
    if (blk < 1024) {
        // buildF: F[b][n][64] = [xyz(3) | points(61)]
        int b = blk >> 7;
        int n0 = (blk & 127) * 64;
        int nl = tid & 63;
        int cl = tid >> 6;
        for (int c = cl; c < 64; c += 4) {
            int n = n0 + nl;
            float v = (c < 3) ? xyz[((size_t)b * 3 + c) * Nn + n]
                              : pts[((size_t)b * 61 + (c - 3)) * Nn + n];
            tile[c][nl] = v;
        }
        __syncthreads();
        int c = tid & 63;
        int nb = tid >> 6;
        for (int nn = nb; nn < 64; nn += 4)
            g_F[((size_t)(b * Nn + n0 + nn)) * 64 + c] = tile[c][nn];
    } else if (blk < 1056) {
        // fold W0, W1 -> interleaved pair layout
        int t = (blk - 1024) * 256 + tid;
        if (t < 4096) {
            int o = t >> 6, c = t & 63;
            float sc = g0[o] / sqrtf(v0[o] + EPSc);
            g_W0p[(o >> 1) * 136 + c * 2 + (o & 1)] = w0[t] * sc;
            if (c == 0) g_b0[o] = (b0[o] - m0[o]) * sc + be0[o];
        } else {
            int i = t - 4096;
            int o = i >> 6, c = i & 63;
            float sc = g1[o] / sqrtf(v1[o] + EPSc);
            g_W1p[(o >> 1) * 136 + c * 2 + (o & 1)] = w1[i] * sc;
            if (c == 0) g_b1[o] = (b1[o] - m1[o]) * sc + be1[o];
        }
    } else if (blk < 1088) {
        int i = (blk - 1056) * 256 + tid;     // < 8192
        int o = i >> 6, c = i & 63;
        float sc = g2[o] / sqrtf(v2[o] + EPSc);
        g_W2p[(o >> 1) * 136 + c * 2 + (o & 1)] = w2[i] * sc;
        if (c == 0) g_b2[o] = (b2[o] - m2[o]) * sc + be2[o];
    } else {
        // a[131][128] -> g_Ap[tile][pair][cc][2]
        int e = (blk - 1088) * 256 + tid;
        if (e < 131 * 128) {
            int c = e >> 7, d = e & 127;
            int tt = c >> 6, cc = c & 63;
            g_Ap[tt * 8704 + (d >> 1) * 136 + cc * 2 + (d & 1)] = a[(size_t)c * 128 + d];
        }
    }
}

// ---------------- ball query + center gather: one warp per group ----------------
__global__ void __launch_bounds__(256) ball_gather_kernel(const float* __restrict__ xyz,
                                                          const int* __restrict__ tgt,
                                                          float* __restrict__ out) {
    int gw = blockIdx.x * 8 + (threadIdx.x >> 5);
    int lane = threadIdx.x & 31;
    int b = gw >> 11, s = gw & 2047;
    int ci = g_fps_idx[gw];
    const float* xb = xyz + (size_t)b * 3 * Nn;
    float cx = xb[ci];
    float cy = xb[Nn + ci];
    float cz = xb[2 * Nn + ci];
    if (lane == 0) {
        g_newxyz[gw * 3 + 0] = cx;
        g_newxyz[gw * 3 + 1] = cy;
        g_newxyz[gw * 3 + 2] = cz;
        out[((size_t)b * 3 + 0) * Ss + s] = cx;
        out[((size_t)b * 3 + 1) * Ss + s] = cy;
        out[((size_t)b * 3 + 2) * Ss + s] = cz;
        out[(size_t)Bb * 3 * Ss + (size_t)Bb * 128 * Ss + gw] = (float)tgt[(size_t)b * Nn + ci];
    }
    int cnt = 0, firstn = 0;
    for (int base = 0; base < Nn; base += 32) {
        int n = base + lane;
        float dx = xb[n] - cx, dy = xb[Nn + n] - cy, dz = xb[2 * Nn + n] - cz;
        float d = dx * dx + dy * dy + dz * dz;
        bool inb = (d <= 0.25f);
        unsigned m = __ballot_sync(0xffffffffu, inb);
        if (cnt == 0 && m) firstn = base + __ffs(m) - 1;
        int pos = cnt + __popc(m & ((1u << lane) - 1u));
        if (inb && pos < Kk) g_ball_idx[(size_t)gw * Kk + pos] = n;
        cnt += __popc(m);
        if (cnt >= Kk) break;
    }
    for (int j = cnt + lane; j < Kk; j += 32)
        g_ball_idx[(size_t)gw * Kk + j] = firstn;
}

// ============================================================================
// Fused MLP + attention with packed f32x2 FMA. 2 groups/block, 256 threads,
// 108 KB smem -> 2 CTAs/SM. Output PAIRS (2q,2q+1) share one f32x2 lane pair.
// ============================================================================
#define GSTR 68
#define GROWS 2244          // 33*68
#define GFSTR 132
#define GFROWS 4356         // 33*132
#define CATROWS 4224        // 32*132

template <int COUT, int OSTR, int OROWS>
__device__ __forceinline__ void mlp_layer(const float* __restrict__ Wgp,
                                          const float* __restrict__ bg,
                                          float* Wsh, float* bsh,
                                          const float* in, float* out, int tid) {
    constexpr int NPAIR = COUT / 2;
    __syncthreads();
    {
        const float4* src = (const float4*)Wgp;
        float4* dst = (float4*)Wsh;
        for (int idx = tid; idx < NPAIR * 34; idx += 256) dst[idx] = src[idx];
    }
    if (tid < COUT) bsh[tid] = bg[tid];
    __syncthreads();

    constexpr int T = COUT / 32;                 // output-pairs per thread
    int team = tid >> 7, l = tid & 127, po = l & 7, og = l >> 3;
    const float* inb = in + team * GROWS;
    float* outb = out + team * OROWS;

    u64 acc2[4 * T];
#pragma unroll
    for (int i = 0; i < 4 * T; i++) acc2[i] = 0ull;

#pragma unroll 2
    for (int cc = 0; cc < 16; cc++) {
        u64 ivd[4][4];
#pragma unroll
        for (int pp = 0; pp < 4; pp++) {
            float4 iv = *(const float4*)(inb + (po + 8 * pp) * GSTR + cc * 4);
            PACKX2(ivd[pp][0], iv.x, iv.x);
            PACKX2(ivd[pp][1], iv.y, iv.y);
            PACKX2(ivd[pp][2], iv.z, iv.z);
            PACKX2(ivd[pp][3], iv.w, iv.w);
        }
#pragma unroll
        for (int t = 0; t < T; t++) {
            int q = og + 16 * t;
            ulonglong2 w01 = *(const ulonglong2*)(Wsh + q * 136 + cc * 8);
            ulonglong2 w23 = *(const ulonglong2*)(Wsh + q * 136 + cc * 8 + 4);
#pragma unroll
            for (int pp = 0; pp < 4; pp++) {
                FMAX2(acc2[pp * T + t], ivd[pp][0], w01.x, acc2[pp * T + t]);
                FMAX2(acc2[pp * T + t], ivd[pp][1], w01.y, acc2[pp * T + t]);
                FMAX2(acc2[pp * T + t], ivd[pp][2], w23.x, acc2[pp * T + t]);
                FMAX2(acc2[pp * T + t], ivd[pp][3], w23.y, acc2[pp * T + t]);
            }
        }
    }
#pragma unroll
    for (int t = 0; t < T; t++) {
        int q = og + 16 * t;
        float blo = bsh[2 * q], bhi = bsh[2 * q + 1];
#pragma unroll
        for (int pp = 0; pp < 4; pp++) {
            float lo, hi;
            UNPACKX2(lo, hi, acc2[pp * T + t]);
            outb[(po + 8 * pp) * OSTR + 2 * q]     = fmaxf(lo + blo, 0.0f);
            outb[(po + 8 * pp) * OSTR + 2 * q + 1] = fmaxf(hi + bhi, 0.0f);
        }
    }
    // center rows (p = 32), 2 groups (weights read from interleaved layout)
    for (int idx = tid; idx < COUT * 2; idx += 256) {
        int o = idx & (COUT - 1);
        int grp = idx / COUT;
        const float* ir = in + grp * GROWS + 32 * GSTR;
        const float* wr = Wsh + (o >> 1) * 136 + (o & 1);
        float s = 0.0f;
#pragma unroll 8
        for (int c = 0; c < 64; c++) s += ir[c] * wr[c * 2];
        out[grp * OROWS + 32 * OSTR + o] = fmaxf(s + bsh[o], 0.0f);
    }
}

__device__ __forceinline__ void attn_reduce(float* e, int d, const float* gfb,
                                            int po, int team, float* outv) {
    const unsigned FULL = 0xffffffffu;
    float mx = -1e30f;
#pragma unroll
    for (int pp = 0; pp < 4; pp++) {
        float v = e[pp];
        v = (v >= 0.0f) ? v : (ALPHAc * v);
        e[pp] = v;
        mx = fmaxf(mx, v);
    }
    mx = fmaxf(mx, __shfl_xor_sync(FULL, mx, 1));
    mx = fmaxf(mx, __shfl_xor_sync(FULL, mx, 2));
    mx = fmaxf(mx, __shfl_xor_sync(FULL, mx, 4));
    float den = 0.0f;
#pragma unroll
    for (int pp = 0; pp < 4; pp++) { e[pp] = expf(e[pp] - mx); den += e[pp]; }
    den += __shfl_xor_sync(FULL, den, 1);
    den += __shfl_xor_sync(FULL, den, 2);
    den += __shfl_xor_sync(FULL, den, 4);
    float rd = 1.0f / den;
    float val = 0.0f;
#pragma unroll
    for (int pp = 0; pp < 4; pp++)
        val += e[pp] * rd * gfb[(po + 8 * pp) * GFSTR + d];
    val += __shfl_xor_sync(FULL, val, 1);
    val += __shfl_xor_sync(FULL, val, 2);
    val += __shfl_xor_sync(FULL, val, 4);
    if (po == 0) outv[d * 2 + team] = val;
}

__global__ void __launch_bounds__(256) fused_kernel(float* __restrict__ d_out) {
    extern __shared__ float sm[];
    float* bufA = sm;                  // 4488
    float* bufB = sm + 4488;           // 4488
    float* gf   = sm + 8976;           // 8712
    float* Wsh  = sm + 17688;          // 8704
    float* bsh  = sm + 26392;          // 128
    float* dpx  = sm + 26520;          // 64
    float* dpy  = sm + 26584;          // 64
    float* dpz  = sm + 26648;          // 64
    float* outv = sm + 26712;          // 256

    int tid = threadIdx.x;
    int w = tid >> 5, lane = tid & 31;
    int g0 = blockIdx.x * 2;
    int bB = g0 >> 11;

    // ---- load 2*33 feature rows ----
#pragma unroll
    for (int grp = 0; grp < 2; grp++) {
        int g = g0 + grp;
        for (int p = w; p < 33; p += 8) {
            int src = (p < 32) ? g_ball_idx[(size_t)g * Kk + p] : g_fps_idx[g];
            float2 v = ((const float2*)(g_F + (size_t)(bB * Nn + src) * 64))[lane];
            bufA[grp * GROWS + p * GSTR + lane * 2]     = v.x;
            bufA[grp * GROWS + p * GSTR + lane * 2 + 1] = v.y;
        }
    }
    __syncthreads();
    if (tid < 64) {
        int grp = tid >> 5, k = tid & 31;
        int g = g0 + grp;
        float nx = g_newxyz[g * 3 + 0];
        float ny = g_newxyz[g * 3 + 1];
        float nz = g_newxyz[g * 3 + 2];
        float* row = bufA + grp * GROWS + k * GSTR;
        float gx = row[0], gy = row[1], gz = row[2];
        row[0] = gx - nx; row[1] = gy - ny; row[2] = gz - nz;   // grouped_norm
        dpx[grp * 32 + k] = nx - gx;                            // delta_p
        dpy[grp * 32 + k] = ny - gy;
        dpz[grp * 32 + k] = nz - gz;
    }

    // ---- 3-layer MLP (f32x2) ----
    mlp_layer<64, GSTR, GROWS>(g_W0p, g_b0, Wsh, bsh, bufA, bufB, tid);
    mlp_layer<64, GSTR, GROWS>(g_W1p, g_b1, Wsh, bsh, bufB, bufA, tid);
    mlp_layer<128, GFSTR, GFROWS>(g_W2p, g_b2, Wsh, bsh, bufA, gf, tid);
    __syncthreads();

    // ---- build cat[2][32][132] = [delta_p(3) | cf - gf (128) | 0] ----
    float* cat = bufA;
    for (int idx = tid; idx < 2 * 32 * 131; idx += 256) {
        int grp = idx / (32 * 131);
        int r = idx - grp * (32 * 131);
        int k = r / 131;
        int c = r - k * 131;
        const float* gfb = gf + grp * GFROWS;
        float v;
        if (c == 0)      v = dpx[grp * 32 + k];
        else if (c == 1) v = dpy[grp * 32 + k];
        else if (c == 2) v = dpz[grp * 32 + k];
        else             v = gfb[32 * GFSTR + (c - 3)] - gfb[k * GFSTR + (c - 3)];
        cat[grp * CATROWS + k * GFSTR + c] = v;
    }
    if (tid < 64) cat[(tid >> 5) * CATROWS + (tid & 31) * GFSTR + 131] = 0.0f;

    // ---- e = cat @ a  (131 -> 128): f32x2, 4pt x 4 output-pairs ----
    int team = tid >> 7, l = tid & 127, po = l & 7, og = l >> 3;
    const float* catb = cat + team * CATROWS;
    u64 acc2[16];
#pragma unroll
    for (int i = 0; i < 16; i++) acc2[i] = 0ull;

    for (int t = 0; t < 3; t++) {
        __syncthreads();
        if (t < 2) {
            const float4* src = (const float4*)(g_Ap + t * 8704);
            float4* dst = (float4*)Wsh;
            for (int idx = tid; idx < 2176; idx += 256) dst[idx] = src[idx];
        } else {
            for (int idx = tid; idx < 512; idx += 256) {
                int q = idx >> 3, ww = idx & 7;
                Wsh[q * 136 + ww] = g_Ap[2 * 8704 + q * 136 + ww];
            }
        }
        __syncthreads();
        int c0 = t * 64;
        int nch = (t < 2) ? 16 : 1;
#pragma unroll 2
        for (int cc = 0; cc < nch; cc++) {
            u64 ivd[4][4];
#pragma unroll
            for (int pp = 0; pp < 4; pp++) {
                float4 iv = *(const float4*)(catb + (po + 8 * pp) * GFSTR + c0 + cc * 4);
                PACKX2(ivd[pp][0], iv.x, iv.x);
                PACKX2(ivd[pp][1], iv.y, iv.y);
                PACKX2(ivd[pp][2], iv.z, iv.z);
                PACKX2(ivd[pp][3], iv.w, iv.w);
            }
#pragma unroll
            for (int tq = 0; tq < 4; tq++) {
                int q = og + 16 * tq;
                ulonglong2 w01 = *(const ulonglong2*)(Wsh + q * 136 + cc * 8);
                ulonglong2 w23 = *(const ulonglong2*)(Wsh + q * 136 + cc * 8 + 4);
#pragma unroll
                for (int pp = 0; pp < 4; pp++) {
                    FMAX2(acc2[pp * 4 + tq], ivd[pp][0], w01.x, acc2[pp * 4 + tq]);
                    FMAX2(acc2[pp * 4 + tq], ivd[pp][1], w01.y, acc2[pp * 4 + tq]);
                    FMAX2(acc2[pp * 4 + tq], ivd[pp][2], w23.x, acc2[pp * 4 + tq]);
                    FMAX2(acc2[pp * 4 + tq], ivd[pp][3], w23.y, acc2[pp * 4 + tq]);
                }
            }
        }
    }

    // ---- leaky relu + softmax over k + weighted sum ----
    const float* gfb = gf + team * GFROWS;
#pragma unroll
    for (int tq = 0; tq < 4; tq++) {
        int q = og + 16 * tq;
        float elo[4], ehi[4];
#pragma unroll
        for (int pp = 0; pp < 4; pp++)
            UNPACKX2(elo[pp], ehi[pp], acc2[pp * 4 + tq]);
        attn_reduce(elo, 2 * q,     gfb, po, team, outv);
        attn_reduce(ehi, 2 * q + 1, gfb, po, team, outv);
    }
    __syncthreads();

    // ---- coalesced output: 2 consecutive s per d ----
    if (tid < 128) {
        float2 v = *(const float2*)(outv + tid * 2);
        int s0 = g0 & 2047;
        *(float2*)(d_out + (size_t)Bb * 3 * Ss + (size_t)bB * 128 * Ss
                   + (size_t)tid * Ss + s0) = v;
    }
}

// ---------------- launch ----------------
extern "C" void kernel_launch(void* const* d_in, const int* in_sizes, int n_in,
                              void* d_out, int out_size) {
    const float* xyz = (const float*)d_in[0];
    const float* pts = (const float*)d_in[1];
    const int*   tgt = (const int*)d_in[2];
    const float* w0 = (const float*)d_in[3];
    const float* b0 = (const float*)d_in[4];
    const float* g0 = (const float*)d_in[5];
    const float* be0 = (const float*)d_in[6];
    const float* m0 = (const float*)d_in[7];
    const float* v0 = (const float*)d_in[8];
    const float* w1 = (const float*)d_in[9];
    const float* b1 = (const float*)d_in[10];
    const float* g1 = (const float*)d_in[11];
    const float* be1 = (const float*)d_in[12];
    const float* m1 = (const float*)d_in[13];
    const float* v1 = (const float*)d_in[14];
    const float* w2 = (const float*)d_in[15];
    const float* b2 = (const float*)d_in[16];
    const float* g2 = (const float*)d_in[17];
    const float* be2 = (const float*)d_in[18];
    const float* m2 = (const float*)d_in[19];
    const float* v2 = (const float*)d_in[20];
    const float* a  = (const float*)d_in[21];
    float* out = (float*)d_out;

    cudaFuncSetAttribute(fps_kernel, cudaFuncAttributeMaxDynamicSharedMemorySize, Nn * 16);
    cudaFuncSetAttribute(fused_kernel, cudaFuncAttributeMaxDynamicSharedMemorySize, 26968 * 4);

    // 4 launches; profiled slot (4th) = fused_kernel
    prep_kernel<<<1154, 256>>>(xyz, pts,
                               w0, b0, g0, be0, m0, v0,
                               w1, b1, g1, be1, m1, v1,
                               w2, b2, g2, be2, m2, v2, a);
    fps_kernel<<<Bb, 1024, Nn * 16>>>(xyz);
    ball_gather_kernel<<<(Bb * Ss) / 8, 256>>>(xyz, tgt, out);
    fused_kernel<<<Bb * Ss / 2, 256, 26968 * 4>>>(out);
}

// round 7
// speedup vs baseline: 1.9726x; 1.5933x over previous
#include <cuda_runtime.h>
#include <cuda_bf16.h>
#include <math.h>

#define Bb 8
#define Nn 8192
#define Ss 2048
#define Kk 32
#define EPSc 1e-5f
#define ALPHAc 0.2f

typedef unsigned long long u64;

// ---- packed f32x2 helpers (Blackwell) ----
#define PACKX2(out, lo, hi) \
    asm("mov.b64 %0, {%1, %2};" : "=l"(out) : "f"(lo), "f"(hi))
#define UNPACKX2(lo, hi, in) \
    asm("mov.b64 {%0, %1}, %2;" : "=f"(lo), "=f"(hi) : "l"(in))
#define ADDX2(d, a, b) \
    asm("add.rn.f32x2 %0, %1, %2;" : "=l"(d) : "l"(a), "l"(b))
#define MULX2(d, a, b) \
    asm("mul.rn.f32x2 %0, %1, %2;" : "=l"(d) : "l"(a), "l"(b))
#define FMAX2(d, a, b, c) \
    asm("fma.rn.f32x2 %0, %1, %2, %3;" : "=l"(d) : "l"(a), "l"(b), "l"(c))

// ---------------- scratch (device globals; no allocations) ----------------
__device__ int   g_fps_idx[Bb * Ss];
__device__ int   g_ball_idx[Bb * Ss * Kk];
__device__ float g_newxyz[Bb * Ss * 3];
__device__ __align__(16) float g_F[(size_t)Bb * Nn * 64];   // [xyz(3)|points(61)]
// interleaved weights: Wp[pair][c][2], row pad 136 floats
__device__ __align__(16) float g_W0p[32 * 136];
__device__ __align__(16) float g_W1p[32 * 136];
__device__ __align__(16) float g_W2p[64 * 136];
__device__ __align__(16) float g_Ap[3 * 8704];               // a interleaved, 3 c-tiles
__device__ float g_b0[64], g_b1[64], g_b2[128];

// ============================================================================
// FPS: one block per batch, 512 threads x 16 points, REDUX reductions.
// Distances >= 0 -> float bits monotone as u32 -> argmax via redux.max.u32 on
// bits + redux.min.u32 on candidate idx (exact first-max tie-break preserved).
// ============================================================================
__global__ void __launch_bounds__(512) fps_kernel(const float* __restrict__ xyz) {
    extern __shared__ float4 pts4[];                 // 8192 float4 = 128 KB
    __shared__ unsigned rv[2][16];
    __shared__ int      ri[2][16];

    int b = blockIdx.x;
    int tid = threadIdx.x;
    int lane = tid & 31, wid = tid >> 5;             // 16 warps
    const unsigned FULL = 0xffffffffu;

    float xr[16], yr[16], zr[16], dd[16];
    u64 px2[8], py2[8], pz2[8];
#pragma unroll
    for (int j = 0; j < 16; j++) {
        int i = tid + j * 512;
        xr[j] = xyz[((size_t)b * 3 + 0) * Nn + i];
        yr[j] = xyz[((size_t)b * 3 + 1) * Nn + i];
        zr[j] = xyz[((size_t)b * 3 + 2) * Nn + i];
        pts4[i] = make_float4(xr[j], yr[j], zr[j], 0.0f);
        dd[j] = 1e10f;
    }
#pragma unroll
    for (int m = 0; m < 8; m++) {
        PACKX2(px2[m], xr[2 * m], xr[2 * m + 1]);
        PACKX2(py2[m], yr[2 * m], yr[2 * m + 1]);
        PACKX2(pz2[m], zr[2 * m], zr[2 * m + 1]);
    }
    __syncthreads();

    int cur = 0;
    for (int s = 0; s < Ss; s++) {
        if (tid == 0) g_fps_idx[b * Ss + s] = cur;
        float4 c = pts4[cur];
        float ncx = -c.x, ncy = -c.y, ncz = -c.z;
        u64 cx2, cy2, cz2;
        PACKX2(cx2, ncx, ncx);
        PACKX2(cy2, ncy, ncy);
        PACKX2(cz2, ncz, ncz);

        float best = -1.0f; int bi = 0;
#pragma unroll
        for (int m = 0; m < 8; m++) {
            u64 dx2, dy2, dz2, t2;
            ADDX2(dx2, px2[m], cx2);
            ADDX2(dy2, py2[m], cy2);
            ADDX2(dz2, pz2[m], cz2);
            MULX2(t2, dx2, dx2);
            FMAX2(t2, dy2, dy2, t2);
            FMAX2(t2, dz2, dz2, t2);
            float dl, dh;
            UNPACKX2(dl, dh, t2);
            float n0 = fminf(dd[2 * m], dl);     dd[2 * m] = n0;
            float n1 = fminf(dd[2 * m + 1], dh); dd[2 * m + 1] = n1;
            if (n0 > best) { best = n0; bi = tid + (2 * m) * 512; }       // ascending idx
            if (n1 > best) { best = n1; bi = tid + (2 * m + 1) * 512; }
        }
        // stage 1: warp argmax via REDUX (exact smallest-idx tie-break)
        unsigned key = __float_as_uint(best);
        unsigned wkey = __reduce_max_sync(FULL, key);
        unsigned cand = (key == wkey) ? (unsigned)bi : 0xffffffffu;
        unsigned wbi = __reduce_min_sync(FULL, cand);

        int par = s & 1;
        if (lane == 0) { rv[par][wid] = wkey; ri[par][wid] = (int)wbi; }
        __syncthreads();

        // stage 2: 16 warp results (lanes 16-31 mirror 0-15; harmless for max/min)
        unsigned k2 = rv[par][lane & 15];
        int      i2 = ri[par][lane & 15];
        unsigned m2 = __reduce_max_sync(FULL, k2);
        unsigned c2 = (k2 == m2) ? (unsigned)i2 : 0xffffffffu;
        cur = (int)__reduce_min_sync(FULL, c2);
    }
}

// ---------------- prep A: buildF (transpose features) ----------------
__global__ void __launch_bounds__(256) buildF_kernel(const float* __restrict__ xyz,
                                                     const float* __restrict__ pts) {
    __shared__ float tile[64][65];
    int b = blockIdx.x >> 7;
    int n0 = (blockIdx.x & 127) * 64;
    int tid = threadIdx.x;
    int nl = tid & 63;
    int cl = tid >> 6;
    for (int c = cl; c < 64; c += 4) {
        int n = n0 + nl;
        float v = (c < 3) ? xyz[((size_t)b * 3 + c) * Nn + n]
                          : pts[((size_t)b * 61 + (c - 3)) * Nn + n];
        tile[c][nl] = v;
    }
    __syncthreads();
    int c = tid & 63;
    int nb = tid >> 6;
    for (int nn = nb; nn < 64; nn += 4)
        g_F[((size_t)(b * Nn + n0 + nn)) * 64 + c] = tile[c][nn];
}

// ---------------- prep B: fold BN -> interleaved pair weights ----------------
__global__ void __launch_bounds__(256) foldw_kernel(
    const float* w0, const float* b0, const float* g0, const float* be0, const float* m0, const float* v0,
    const float* w1, const float* b1, const float* g1, const float* be1, const float* m1, const float* v1,
    const float* w2, const float* b2, const float* g2, const float* be2, const float* m2, const float* v2) {
    int t = blockIdx.x * 256 + threadIdx.x;
    if (t < 4096) {
        int o = t >> 6, c = t & 63;
        float sc = g0[o] / sqrtf(v0[o] + EPSc);
        g_W0p[(o >> 1) * 136 + c * 2 + (o & 1)] = w0[t] * sc;
        if (c == 0) g_b0[o] = (b0[o] - m0[o]) * sc + be0[o];
    } else if (t < 8192) {
        int i = t - 4096;
        int o = i >> 6, c = i & 63;
        float sc = g1[o] / sqrtf(v1[o] + EPSc);
        g_W1p[(o >> 1) * 136 + c * 2 + (o & 1)] = w1[i] * sc;
        if (c == 0) g_b1[o] = (b1[o] - m1[o]) * sc + be1[o];
    } else if (t < 16384) {
        int i = t - 8192;
        int o = i >> 6, c = i & 63;
        float sc = g2[o] / sqrtf(v2[o] + EPSc);
        g_W2p[(o >> 1) * 136 + c * 2 + (o & 1)] = w2[i] * sc;
        if (c == 0) g_b2[o] = (b2[o] - m2[o]) * sc + be2[o];
    }
}

// ---------------- prep C: interleave attention matrix a ----------------
__global__ void __launch_bounds__(256) folda_kernel(const float* __restrict__ a) {
    int e = blockIdx.x * 256 + threadIdx.x;
    if (e < 131 * 128) {
        int c = e >> 7, d = e & 127;
        int tt = c >> 6, cc = c & 63;
        g_Ap[tt * 8704 + (d >> 1) * 136 + cc * 2 + (d & 1)] = a[(size_t)c * 128 + d];
    }
}

// ---------------- ball query + center gather: one warp per group ----------------
__global__ void __launch_bounds__(256) ball_gather_kernel(const float* __restrict__ xyz,
                                                          const int* __restrict__ tgt,
                                                          float* __restrict__ out) {
    int gw = blockIdx.x * 8 + (threadIdx.x >> 5);
    int lane = threadIdx.x & 31;
    int b = gw >> 11, s = gw & 2047;
    int ci = g_fps_idx[gw];
    const float* xb = xyz + (size_t)b * 3 * Nn;
    float cx = xb[ci];
    float cy = xb[Nn + ci];
    float cz = xb[2 * Nn + ci];
    if (lane == 0) {
        g_newxyz[gw * 3 + 0] = cx;
        g_newxyz[gw * 3 + 1] = cy;
        g_newxyz[gw * 3 + 2] = cz;
        out[((size_t)b * 3 + 0) * Ss + s] = cx;
        out[((size_t)b * 3 + 1) * Ss + s] = cy;
        out[((size_t)b * 3 + 2) * Ss + s] = cz;
        out[(size_t)Bb * 3 * Ss + (size_t)Bb * 128 * Ss + gw] = (float)tgt[(size_t)b * Nn + ci];
    }
    int cnt = 0, firstn = 0;
    for (int base = 0; base < Nn; base += 32) {
        int n = base + lane;
        float dx = xb[n] - cx, dy = xb[Nn + n] - cy, dz = xb[2 * Nn + n] - cz;
        float d = dx * dx + dy * dy + dz * dz;
        bool inb = (d <= 0.25f);
        unsigned m = __ballot_sync(0xffffffffu, inb);
        if (cnt == 0 && m) firstn = base + __ffs(m) - 1;
        int pos = cnt + __popc(m & ((1u << lane) - 1u));
        if (inb && pos < Kk) g_ball_idx[(size_t)gw * Kk + pos] = n;
        cnt += __popc(m);
        if (cnt >= Kk) break;
    }
    for (int j = cnt + lane; j < Kk; j += 32)
        g_ball_idx[(size_t)gw * Kk + j] = firstn;
}

// ============================================================================
// Fused MLP + attention with packed f32x2 FMA. 2 groups/block, 256 threads,
// 108 KB smem -> 2 CTAs/SM. Output PAIRS (2q,2q+1) share one f32x2 lane pair.
// ============================================================================
#define GSTR 68
#define GROWS 2244          // 33*68
#define GFSTR 132
#define GFROWS 4356         // 33*132
#define CATROWS 4224        // 32*132

template <int COUT, int OSTR, int OROWS>
__device__ __forceinline__ void mlp_layer(const float* __restrict__ Wgp,
                                          const float* __restrict__ bg,
                                          float* Wsh, float* bsh,
                                          const float* in, float* out, int tid) {
    constexpr int NPAIR = COUT / 2;
    __syncthreads();
    {
        const float4* src = (const float4*)Wgp;
        float4* dst = (float4*)Wsh;
        for (int idx = tid; idx < NPAIR * 34; idx += 256) dst[idx] = src[idx];
    }
    if (tid < COUT) bsh[tid] = bg[tid];
    __syncthreads();

    constexpr int T = COUT / 32;                 // output-pairs per thread
    int team = tid >> 7, l = tid & 127, po = l & 7, og = l >> 3;
    const float* inb = in + team * GROWS;
    float* outb = out + team * OROWS;

    u64 acc2[4 * T];
#pragma unroll
    for (int i = 0; i < 4 * T; i++) acc2[i] = 0ull;

#pragma unroll 2
    for (int cc = 0; cc < 16; cc++) {
        u64 ivd[4][4];
#pragma unroll
        for (int pp = 0; pp < 4; pp++) {
            float4 iv = *(const float4*)(inb + (po + 8 * pp) * GSTR + cc * 4);
            PACKX2(ivd[pp][0], iv.x, iv.x);
            PACKX2(ivd[pp][1], iv.y, iv.y);
            PACKX2(ivd[pp][2], iv.z, iv.z);
            PACKX2(ivd[pp][3], iv.w, iv.w);
        }
#pragma unroll
        for (int t = 0; t < T; t++) {
            int q = og + 16 * t;
            ulonglong2 w01 = *(const ulonglong2*)(Wsh + q * 136 + cc * 8);
            ulonglong2 w23 = *(const ulonglong2*)(Wsh + q * 136 + cc * 8 + 4);
#pragma unroll
            for (int pp = 0; pp < 4; pp++) {
                FMAX2(acc2[pp * T + t], ivd[pp][0], w01.x, acc2[pp * T + t]);
                FMAX2(acc2[pp * T + t], ivd[pp][1], w01.y, acc2[pp * T + t]);
                FMAX2(acc2[pp * T + t], ivd[pp][2], w23.x, acc2[pp * T + t]);
                FMAX2(acc2[pp * T + t], ivd[pp][3], w23.y, acc2[pp * T + t]);
            }
        }
    }
#pragma unroll
    for (int t = 0; t < T; t++) {
        int q = og + 16 * t;
        float blo = bsh[2 * q], bhi = bsh[2 * q + 1];
#pragma unroll
        for (int pp = 0; pp < 4; pp++) {
            float lo, hi;
            UNPACKX2(lo, hi, acc2[pp * T + t]);
            outb[(po + 8 * pp) * OSTR + 2 * q]     = fmaxf(lo + blo, 0.0f);
            outb[(po + 8 * pp) * OSTR + 2 * q + 1] = fmaxf(hi + bhi, 0.0f);
        }
    }
    // center rows (p = 32), 2 groups (weights read from interleaved layout)
    for (int idx = tid; idx < COUT * 2; idx += 256) {
        int o = idx & (COUT - 1);
        int grp = idx / COUT;
        const float* ir = in + grp * GROWS + 32 * GSTR;
        const float* wr = Wsh + (o >> 1) * 136 + (o & 1);
        float s = 0.0f;
#pragma unroll 8
        for (int c = 0; c < 64; c++) s += ir[c] * wr[c * 2];
        out[grp * OROWS + 32 * OSTR + o] = fmaxf(s + bsh[o], 0.0f);
    }
}

__device__ __forceinline__ void attn_reduce(float* e, int d, const float* gfb,
                                            int po, int team, float* outv) {
    const unsigned FULL = 0xffffffffu;
    float mx = -1e30f;
#pragma unroll
    for (int pp = 0; pp < 4; pp++) {
        float v = e[pp];
        v = (v >= 0.0f) ? v : (ALPHAc * v);
        e[pp] = v;
        mx = fmaxf(mx, v);
    }
    mx = fmaxf(mx, __shfl_xor_sync(FULL, mx, 1));
    mx = fmaxf(mx, __shfl_xor_sync(FULL, mx, 2));
    mx = fmaxf(mx, __shfl_xor_sync(FULL, mx, 4));
    float den = 0.0f;
#pragma unroll
    for (int pp = 0; pp < 4; pp++) { e[pp] = expf(e[pp] - mx); den += e[pp]; }
    den += __shfl_xor_sync(FULL, den, 1);
    den += __shfl_xor_sync(FULL, den, 2);
    den += __shfl_xor_sync(FULL, den, 4);
    float rd = 1.0f / den;
    float val = 0.0f;
#pragma unroll
    for (int pp = 0; pp < 4; pp++)
        val += e[pp] * rd * gfb[(po + 8 * pp) * GFSTR + d];
    val += __shfl_xor_sync(FULL, val, 1);
    val += __shfl_xor_sync(FULL, val, 2);
    val += __shfl_xor_sync(FULL, val, 4);
    if (po == 0) outv[d * 2 + team] = val;
}

__global__ void __launch_bounds__(256) fused_kernel(float* __restrict__ d_out) {
    extern __shared__ float sm[];
    float* bufA = sm;                  // 4488
    float* bufB = sm + 4488;           // 4488
    float* gf   = sm + 8976;           // 8712
    float* Wsh  = sm + 17688;          // 8704
    float* bsh  = sm + 26392;          // 128
    float* dpx  = sm + 26520;          // 64
    float* dpy  = sm + 26584;          // 64
    float* dpz  = sm + 26648;          // 64
    float* outv = sm + 26712;          // 256

    int tid = threadIdx.x;
    int w = tid >> 5, lane = tid & 31;
    int g0 = blockIdx.x * 2;
    int bB = g0 >> 11;

    // ---- load 2*33 feature rows ----
#pragma unroll
    for (int grp = 0; grp < 2; grp++) {
        int g = g0 + grp;
        for (int p = w; p < 33; p += 8) {
            int src = (p < 32) ? g_ball_idx[(size_t)g * Kk + p] : g_fps_idx[g];
            float2 v = ((const float2*)(g_F + (size_t)(bB * Nn + src) * 64))[lane];
            bufA[grp * GROWS + p * GSTR + lane * 2]     = v.x;
            bufA[grp * GROWS + p * GSTR + lane * 2 + 1] = v.y;
        }
    }
    __syncthreads();
    if (tid < 64) {
        int grp = tid >> 5, k = tid & 31;
        int g = g0 + grp;
        float nx = g_newxyz[g * 3 + 0];
        float ny = g_newxyz[g * 3 + 1];
        float nz = g_newxyz[g * 3 + 2];
        float* row = bufA + grp * GROWS + k * GSTR;
        float gx = row[0], gy = row[1], gz = row[2];
        row[0] = gx - nx; row[1] = gy - ny; row[2] = gz - nz;   // grouped_norm
        dpx[grp * 32 + k] = nx - gx;                            // delta_p
        dpy[grp * 32 + k] = ny - gy;
        dpz[grp * 32 + k] = nz - gz;
    }

    // ---- 3-layer MLP (f32x2) ----
    mlp_layer<64, GSTR, GROWS>(g_W0p, g_b0, Wsh, bsh, bufA, bufB, tid);
    mlp_layer<64, GSTR, GROWS>(g_W1p, g_b1, Wsh, bsh, bufB, bufA, tid);
    mlp_layer<128, GFSTR, GFROWS>(g_W2p, g_b2, Wsh, bsh, bufA, gf, tid);
    __syncthreads();

    // ---- build cat[2][32][132] = [delta_p(3) | cf - gf (128) | 0] ----
    float* cat = bufA;
    for (int idx = tid; idx < 2 * 32 * 131; idx += 256) {
        int grp = idx / (32 * 131);
        int r = idx - grp * (32 * 131);
        int k = r / 131;
        int c = r - k * 131;
        const float* gfb = gf + grp * GFROWS;
        float v;
        if (c == 0)      v = dpx[grp * 32 + k];
        else if (c == 1) v = dpy[grp * 32 + k];
        else if (c == 2) v = dpz[grp * 32 + k];
        else             v = gfb[32 * GFSTR + (c - 3)] - gfb[k * GFSTR + (c - 3)];
        cat[grp * CATROWS + k * GFSTR + c] = v;
    }
    if (tid < 64) cat[(tid >> 5) * CATROWS + (tid & 31) * GFSTR + 131] = 0.0f;

    // ---- e = cat @ a  (131 -> 128): f32x2, 4pt x 4 output-pairs ----
    int team = tid >> 7, l = tid & 127, po = l & 7, og = l >> 3;
    const float* catb = cat + team * CATROWS;
    u64 acc2[16];
#pragma unroll
    for (int i = 0; i < 16; i++) acc2[i] = 0ull;

    for (int t = 0; t < 3; t++) {
        __syncthreads();
        if (t < 2) {
            const float4* src = (const float4*)(g_Ap + t * 8704);
            float4* dst = (float4*)Wsh;
            for (int idx = tid; idx < 2176; idx += 256) dst[idx] = src[idx];
        } else {
            for (int idx = tid; idx < 512; idx += 256) {
                int q = idx >> 3, ww = idx & 7;
                Wsh[q * 136 + ww] = g_Ap[2 * 8704 + q * 136 + ww];
            }
        }
        __syncthreads();
        int c0 = t * 64;
        int nch = (t < 2) ? 16 : 1;
#pragma unroll 2
        for (int cc = 0; cc < nch; cc++) {
            u64 ivd[4][4];
#pragma unroll
            for (int pp = 0; pp < 4; pp++) {
                float4 iv = *(const float4*)(catb + (po + 8 * pp) * GFSTR + c0 + cc * 4);
                PACKX2(ivd[pp][0], iv.x, iv.x);
                PACKX2(ivd[pp][1], iv.y, iv.y);
                PACKX2(ivd[pp][2], iv.z, iv.z);
                PACKX2(ivd[pp][3], iv.w, iv.w);
            }
#pragma unroll
            for (int tq = 0; tq < 4; tq++) {
                int q = og + 16 * tq;
                ulonglong2 w01 = *(const ulonglong2*)(Wsh + q * 136 + cc * 8);
                ulonglong2 w23 = *(const ulonglong2*)(Wsh + q * 136 + cc * 8 + 4);
#pragma unroll
                for (int pp = 0; pp < 4; pp++) {
                    FMAX2(acc2[pp * 4 + tq], ivd[pp][0], w01.x, acc2[pp * 4 + tq]);
                    FMAX2(acc2[pp * 4 + tq], ivd[pp][1], w01.y, acc2[pp * 4 + tq]);
                    FMAX2(acc2[pp * 4 + tq], ivd[pp][2], w23.x, acc2[pp * 4 + tq]);
                    FMAX2(acc2[pp * 4 + tq], ivd[pp][3], w23.y, acc2[pp * 4 + tq]);
                }
            }
        }
    }

    // ---- leaky relu + softmax over k + weighted sum ----
    const float* gfb = gf + team * GFROWS;
#pragma unroll
    for (int tq = 0; tq < 4; tq++) {
        int q = og + 16 * tq;
        float elo[4], ehi[4];
#pragma unroll
        for (int pp = 0; pp < 4; pp++)
            UNPACKX2(elo[pp], ehi[pp], acc2[pp * 4 + tq]);
        attn_reduce(elo, 2 * q,     gfb, po, team, outv);
        attn_reduce(ehi, 2 * q + 1, gfb, po, team, outv);
    }
    __syncthreads();

    // ---- coalesced output: 2 consecutive s per d ----
    if (tid < 128) {
        float2 v = *(const float2*)(outv + tid * 2);
        int s0 = g0 & 2047;
        *(float2*)(d_out + (size_t)Bb * 3 * Ss + (size_t)bB * 128 * Ss
                   + (size_t)tid * Ss + s0) = v;
    }
}

// ---------------- launch ----------------
extern "C" void kernel_launch(void* const* d_in, const int* in_sizes, int n_in,
                              void* d_out, int out_size) {
    const float* xyz = (const float*)d_in[0];
    const float* pts = (const float*)d_in[1];
    const int*   tgt = (const int*)d_in[2];
    const float* w0 = (const float*)d_in[3];
    const float* b0 = (const float*)d_in[4];
    const float* g0 = (const float*)d_in[5];
    const float* be0 = (const float*)d_in[6];
    const float* m0 = (const float*)d_in[7];
    const float* v0 = (const float*)d_in[8];
    const float* w1 = (const float*)d_in[9];
    const float* b1 = (const float*)d_in[10];
    const float* g1 = (const float*)d_in[11];
    const float* be1 = (const float*)d_in[12];
    const float* m1 = (const float*)d_in[13];
    const float* v1 = (const float*)d_in[14];
    const float* w2 = (const float*)d_in[15];
    const float* b2 = (const float*)d_in[16];
    const float* g2 = (const float*)d_in[17];
    const float* be2 = (const float*)d_in[18];
    const float* m2 = (const float*)d_in[19];
    const float* v2 = (const float*)d_in[20];
    const float* a  = (const float*)d_in[21];
    float* out = (float*)d_out;

    cudaFuncSetAttribute(fps_kernel, cudaFuncAttributeMaxDynamicSharedMemorySize, Nn * 16);
    cudaFuncSetAttribute(fused_kernel, cudaFuncAttributeMaxDynamicSharedMemorySize, 26968 * 4);

    // 6 launches; profiled slot (4th) = fps_kernel
    buildF_kernel<<<1024, 256>>>(xyz, pts);
    foldw_kernel<<<64, 256>>>(w0, b0, g0, be0, m0, v0,
                              w1, b1, g1, be1, m1, v1,
                              w2, b2, g2, be2, m2, v2);
    folda_kernel<<<66, 256>>>(a);
    fps_kernel<<<Bb, 512, Nn * 16>>>(xyz);
    ball_gather_kernel<<<(Bb * Ss) / 8, 256>>>(xyz, tgt, out);
    fused_kernel<<<Bb * Ss / 2, 256, 26968 * 4>>>(out);
}